// round 11
// baseline (speedup 1.0000x reference)
#include <cuda_runtime.h>
#include <cuda_fp16.h>
#include <math.h>
#include <stdint.h>

#define NN 4096
#define CC 256
#define HH 8
#define DHH 32
#define LL 3
#define EPSV 1e-5f
#define QSC (0.17677669529663687f * 1.4426950408889634f)

// ---------------- scratch (no allocation allowed) ----------------
__device__ float g_h[NN*CC];
__device__ float g_agg[NN*CC];
__device__ float g_t1[NN*2*CC];
__device__ float g_t2[NN*CC];
__device__ float g_q[NN*CC];
__device__ float g_k[NN*CC];
__device__ float g_v[NN*CC];
__device__ float g_o[NN*CC];
__device__ float g_h1[NN*CC];
__device__ float g_sum[9*CC];     // one set per BN instance (3 per layer x 3 layers)
__device__ float g_sumsq[9*CC];

// fp16 hi/lo weight cache (converted each launch; deterministic)
#define OFF_GW1 0
#define OFF_GW2 196608
#define OFF_WQ  393216
#define OFF_WK  589824
#define OFF_WV  786432
#define OFF_WO  983040
#define OFF_MW1 1179648
#define OFF_MW2 1572864
#define TOTW    1966080
__device__ __half g_wh[TOTW];
__device__ __half g_wl[TOTW];

// ---------------- mma helpers ----------------
__device__ __forceinline__ void mma16816(float* d, const uint32_t* a, const uint32_t* b) {
    asm volatile(
        "mma.sync.aligned.m16n8k16.row.col.f32.f16.f16.f32 "
        "{%0,%1,%2,%3}, {%4,%5,%6,%7}, {%8,%9}, {%0,%1,%2,%3};"
        : "+f"(d[0]), "+f"(d[1]), "+f"(d[2]), "+f"(d[3])
        : "r"(a[0]), "r"(a[1]), "r"(a[2]), "r"(a[3]), "r"(b[0]), "r"(b[1]));
}
__device__ __forceinline__ uint32_t packh2(float x, float y) {
    __half2 h = __floats2half2_rn(x, y);
    return *(uint32_t*)&h;
}

// ---------------- weight conversion: all 8 regions, one launch ----------------
__global__ void convw_all_kernel(
    const float* __restrict__ gw1, const float* __restrict__ gw2,
    const float* __restrict__ wq,  const float* __restrict__ wk,
    const float* __restrict__ wv,  const float* __restrict__ wo,
    const float* __restrict__ mw1, const float* __restrict__ mw2)
{
    int i = blockIdx.x*256 + threadIdx.x;
    if (i >= TOTW) return;
    const float* src; int off;
    if      (i < OFF_GW2) { src = gw1; off = OFF_GW1; }
    else if (i < OFF_WQ)  { src = gw2; off = OFF_GW2; }
    else if (i < OFF_WK)  { src = wq;  off = OFF_WQ;  }
    else if (i < OFF_WV)  { src = wk;  off = OFF_WK;  }
    else if (i < OFF_WO)  { src = wv;  off = OFF_WV;  }
    else if (i < OFF_MW1) { src = wo;  off = OFF_WO;  }
    else if (i < OFF_MW2) { src = mw1; off = OFF_MW1; }
    else                  { src = mw2; off = OFF_MW2; }
    float x = src[i - off];
    __half h = __float2half_rn(x);
    g_wh[i] = h;
    g_wl[i] = __float2half_rn(x - __half2float(h));
}

// ---------------- HMMA GEMM (3-term hi/lo split) + optional fused BN-stats ----------------
// If other != null: C = gemm + bias + other (no relu), and per-channel sum/sumsq
// are accumulated into g_sum/g_sumsq at statoff (CTA smem reduction + atomics).
#define APAD 40
__device__ __forceinline__ void gemm_mma_body(
    const float* __restrict__ A1, const float* __restrict__ A2,
    const __half* __restrict__ Bh, const __half* __restrict__ Bl,
    const float* __restrict__ bias, float* __restrict__ C,
    int Nout, int K, int relu,
    const float* __restrict__ other, int statoff,
    int m0, int n0)
{
    __shared__ __half Ah[128][APAD];
    __shared__ __half Al[128][APAD];
    __shared__ __half Bhs[64][APAD];
    __shared__ __half Bls[64][APAD];
    __shared__ float csum[64], csq[64];

    const int tid = threadIdx.x;
    const int w = tid >> 5, lane = tid & 31;
    const int g = lane >> 2, tc = lane & 3;
    const int wm = w & 1, wn = w >> 1;

    float acc[4][4][4] = {};

    for (int k0 = 0; k0 < K; k0 += 32) {
        #pragma unroll
        for (int it = 0; it < 16; it++) {
            int idx = it*128 + tid;
            int r = idx >> 4, c2 = idx & 15;
            const float* p = &A1[(m0 + r)*K + k0 + c2*2];
            float ax = p[0], ay = p[1];
            if (A2) { const float* p2 = &A2[(m0 + r)*K + k0 + c2*2]; ax += p2[0]; ay += p2[1]; }
            __half hx = __float2half_rn(ax), hy = __float2half_rn(ay);
            Ah[r][c2*2]   = hx; Ah[r][c2*2+1] = hy;
            Al[r][c2*2]   = __float2half_rn(ax - __half2float(hx));
            Al[r][c2*2+1] = __float2half_rn(ay - __half2float(hy));
        }
        #pragma unroll
        for (int it = 0; it < 8; it++) {
            int idx = it*128 + tid;
            int r = idx >> 4, c2 = idx & 15;
            *(__half2*)&Bhs[r][c2*2] = *(const __half2*)&Bh[(n0 + r)*K + k0 + c2*2];
            *(__half2*)&Bls[r][c2*2] = *(const __half2*)&Bl[(n0 + r)*K + k0 + c2*2];
        }
        __syncthreads();

        #pragma unroll
        for (int kt = 0; kt < 2; kt++) {
            uint32_t ah[4][4], al[4][4], bh[4][2], bl[4][2];
            #pragma unroll
            for (int mt = 0; mt < 4; mt++) {
                int rb = wm*64 + mt*16 + g;
                int c = kt*16 + 2*tc;
                ah[mt][0] = *(const uint32_t*)&Ah[rb    ][c];
                ah[mt][1] = *(const uint32_t*)&Ah[rb + 8][c];
                ah[mt][2] = *(const uint32_t*)&Ah[rb    ][c + 8];
                ah[mt][3] = *(const uint32_t*)&Ah[rb + 8][c + 8];
                al[mt][0] = *(const uint32_t*)&Al[rb    ][c];
                al[mt][1] = *(const uint32_t*)&Al[rb + 8][c];
                al[mt][2] = *(const uint32_t*)&Al[rb    ][c + 8];
                al[mt][3] = *(const uint32_t*)&Al[rb + 8][c + 8];
            }
            #pragma unroll
            for (int nt = 0; nt < 4; nt++) {
                int nb = wn*32 + nt*8 + g;
                int c = kt*16 + 2*tc;
                bh[nt][0] = *(const uint32_t*)&Bhs[nb][c];
                bh[nt][1] = *(const uint32_t*)&Bhs[nb][c + 8];
                bl[nt][0] = *(const uint32_t*)&Bls[nb][c];
                bl[nt][1] = *(const uint32_t*)&Bls[nb][c + 8];
            }
            #pragma unroll
            for (int mt = 0; mt < 4; mt++)
                #pragma unroll
                for (int nt = 0; nt < 4; nt++) {
                    mma16816(acc[mt][nt], ah[mt], bh[nt]);
                    mma16816(acc[mt][nt], al[mt], bh[nt]);
                    mma16816(acc[mt][nt], ah[mt], bl[nt]);
                }
        }
        __syncthreads();
    }

    if (other) { if (tid < 64) { csum[tid] = 0.f; csq[tid] = 0.f; } __syncthreads(); }

    float ps[4][2] = {}, pq[4][2] = {};
    #pragma unroll
    for (int mt = 0; mt < 4; mt++) {
        int row = m0 + wm*64 + mt*16 + g;
        #pragma unroll
        for (int nt = 0; nt < 4; nt++) {
            int col = n0 + wn*32 + nt*8 + 2*tc;
            float b0 = bias[col], b1 = bias[col + 1];
            float v0 = acc[mt][nt][0] + b0, v1 = acc[mt][nt][1] + b1;
            float v2 = acc[mt][nt][2] + b0, v3 = acc[mt][nt][3] + b1;
            if (relu) {
                v0 = fmaxf(v0, 0.f); v1 = fmaxf(v1, 0.f);
                v2 = fmaxf(v2, 0.f); v3 = fmaxf(v3, 0.f);
            }
            if (other) {
                float2 o0 = *(const float2*)&other[row*Nout + col];
                float2 o1 = *(const float2*)&other[(row + 8)*Nout + col];
                v0 += o0.x; v1 += o0.y; v2 += o1.x; v3 += o1.y;
                ps[nt][0] += v0 + v2;       ps[nt][1] += v1 + v3;
                pq[nt][0] += v0*v0 + v2*v2; pq[nt][1] += v1*v1 + v3*v3;
            }
            *(float2*)&C[row*Nout + col]       = make_float2(v0, v1);
            *(float2*)&C[(row + 8)*Nout + col] = make_float2(v2, v3);
        }
    }
    if (other) {
        #pragma unroll
        for (int nt = 0; nt < 4; nt++) {
            int lc = wn*32 + nt*8 + 2*tc;
            atomicAdd(&csum[lc],     ps[nt][0]); atomicAdd(&csum[lc + 1], ps[nt][1]);
            atomicAdd(&csq[lc],      pq[nt][0]); atomicAdd(&csq[lc + 1],  pq[nt][1]);
        }
        __syncthreads();
        if (tid < 64) {
            atomicAdd(&g_sum[statoff + n0 + tid],   csum[tid]);
            atomicAdd(&g_sumsq[statoff + n0 + tid], csq[tid]);
        }
    }
}

__global__ void __launch_bounds__(128) gemm_mma_kernel(
    const float* __restrict__ A1, const float* __restrict__ A2,
    const __half* __restrict__ Bh, const __half* __restrict__ Bl,
    const float* __restrict__ bias, float* __restrict__ C,
    int Nout, int K, int relu, const float* __restrict__ other, int statoff)
{
    gemm_mma_body(A1, A2, Bh, Bl, bias, C, Nout, K, relu, other, statoff,
                  blockIdx.y*128, blockIdx.x*64);
}

__global__ void __launch_bounds__(128) qkv_mma_kernel(
    const float* __restrict__ A, const __half* __restrict__ wh,
    const __half* __restrict__ wl,
    const float* __restrict__ bq, const float* __restrict__ bk,
    const float* __restrict__ bv,
    float* __restrict__ q, float* __restrict__ k, float* __restrict__ v, int l)
{
    const __half *Bh, *Bl; const float* bias; float* C;
    int woff = l*CC*CC;
    if (blockIdx.z == 0)      { Bh = wh + OFF_WQ + woff; Bl = wl + OFF_WQ + woff; bias = bq; C = q; }
    else if (blockIdx.z == 1) { Bh = wh + OFF_WK + woff; Bl = wl + OFF_WK + woff; bias = bk; C = k; }
    else                      { Bh = wh + OFF_WV + woff; Bl = wl + OFF_WV + woff; bias = bv; C = v; }
    gemm_mma_body(A, nullptr, Bh, Bl, bias, C, CC, CC, 0, nullptr, -1,
                  blockIdx.y*128, blockIdx.x*64);
}

// ---------------- flash attention (fp16 mma, online softmax, skip-rescale) ----------------
#define QPAD 36
#define VPAD 132
__global__ void __launch_bounds__(256) flash_mma_kernel(
    const float* __restrict__ Q, const float* __restrict__ Kp,
    const float* __restrict__ V, float* __restrict__ Og)
{
    __shared__ __half Qs[256][QPAD];
    __shared__ __half Ks[128][QPAD];
    __shared__ __half VTs[32][VPAD];

    const int tid = threadIdx.x;
    const int w = tid >> 5, lane = tid & 31;
    const int g = lane >> 2, tc = lane & 3;
    const int hoff = blockIdx.y * DHH;
    const int q0 = blockIdx.x * 256;

    #pragma unroll
    for (int it = 0; it < 16; it++) {
        int idx = it*256 + tid;
        int r = idx >> 4, pr = idx & 15;
        float2 f = *(const float2*)&Q[(q0 + r)*CC + hoff + pr*2];
        *(__half2*)&Qs[r][pr*2] = __floats2half2_rn(f.x * QSC, f.y * QSC);
    }
    __syncthreads();

    uint32_t qa[2][2][4];
    #pragma unroll
    for (int mt = 0; mt < 2; mt++) {
        #pragma unroll
        for (int kt = 0; kt < 2; kt++) {
            int r0 = w*32 + mt*16 + g;
            qa[mt][kt][0] = *(const uint32_t*)&Qs[r0    ][kt*16 + 2*tc    ];
            qa[mt][kt][1] = *(const uint32_t*)&Qs[r0 + 8][kt*16 + 2*tc    ];
            qa[mt][kt][2] = *(const uint32_t*)&Qs[r0    ][kt*16 + 2*tc + 8];
            qa[mt][kt][3] = *(const uint32_t*)&Qs[r0 + 8][kt*16 + 2*tc + 8];
        }
    }

    float oacc[2][4][4] = {};
    float lacc[4] = {};
    float mrow[4] = {-1e30f, -1e30f, -1e30f, -1e30f};

    for (int j0 = 0; j0 < NN; j0 += 128) {
        __syncthreads();
        #pragma unroll
        for (int it = 0; it < 8; it++) {
            int idx = it*256 + tid;
            int r = idx >> 4, pr = idx & 15;
            float2 f = *(const float2*)&Kp[(j0 + r)*CC + hoff + pr*2];
            *(__half2*)&Ks[r][pr*2] = __floats2half2_rn(f.x, f.y);
        }
        #pragma unroll
        for (int it = 0; it < 8; it++) {
            int idx = it*256 + tid;
            int j = idx >> 4, dp = idx & 15;
            float2 f = *(const float2*)&V[(j0 + j)*CC + hoff + dp*2];
            VTs[dp*2    ][j] = __float2half(f.x);
            VTs[dp*2 + 1][j] = __float2half(f.y);
        }
        __syncthreads();

        #pragma unroll
        for (int ng = 0; ng < 8; ng++) {
            const int kb = ng*16;
            float s[2][2][4] = {};
            #pragma unroll
            for (int kt = 0; kt < 2; kt++) {
                uint32_t b[2][2];
                #pragma unroll
                for (int j = 0; j < 2; j++) {
                    int key = kb + j*8 + g;
                    b[j][0] = *(const uint32_t*)&Ks[key][kt*16 + 2*tc    ];
                    b[j][1] = *(const uint32_t*)&Ks[key][kt*16 + 2*tc + 8];
                }
                #pragma unroll
                for (int mt = 0; mt < 2; mt++)
                    #pragma unroll
                    for (int j = 0; j < 2; j++)
                        mma16816(s[mt][j], qa[mt][kt], b[j]);
            }
            uint32_t pa[2][4];
            #pragma unroll
            for (int mt = 0; mt < 2; mt++) {
                #pragma unroll
                for (int hi = 0; hi < 2; hi++) {
                    float rm = fmaxf(fmaxf(s[mt][0][2*hi], s[mt][0][2*hi+1]),
                                     fmaxf(s[mt][1][2*hi], s[mt][1][2*hi+1]));
                    rm = fmaxf(rm, __shfl_xor_sync(0xffffffffu, rm, 1));
                    rm = fmaxf(rm, __shfl_xor_sync(0xffffffffu, rm, 2));
                    float mold = mrow[mt*2 + hi];
                    float mnew = fmaxf(mold, rm);
                    float p00 = exp2f(s[mt][0][2*hi]   - mnew);
                    float p01 = exp2f(s[mt][0][2*hi+1] - mnew);
                    float p10 = exp2f(s[mt][1][2*hi]   - mnew);
                    float p11 = exp2f(s[mt][1][2*hi+1] - mnew);
                    float psum = p00 + p01 + p10 + p11;
                    if (rm > mold) {
                        float cf = exp2f(mold - mnew);
                        mrow[mt*2 + hi] = mnew;
                        lacc[mt*2 + hi] = lacc[mt*2 + hi]*cf + psum;
                        #pragma unroll
                        for (int dj = 0; dj < 4; dj++) {
                            oacc[mt][dj][2*hi]   *= cf;
                            oacc[mt][dj][2*hi+1] *= cf;
                        }
                    } else {
                        lacc[mt*2 + hi] += psum;
                    }
                    pa[mt][0*2 + hi] = packh2(p00, p01);
                    pa[mt][1*2 + hi] = packh2(p10, p11);
                }
            }
            #pragma unroll
            for (int dj = 0; dj < 4; dj++) {
                uint32_t vb[2];
                vb[0] = *(const uint32_t*)&VTs[dj*8 + g][kb + 2*tc    ];
                vb[1] = *(const uint32_t*)&VTs[dj*8 + g][kb + 2*tc + 8];
                #pragma unroll
                for (int mt = 0; mt < 2; mt++)
                    mma16816(oacc[mt][dj], pa[mt], vb);
            }
        }
    }

    #pragma unroll
    for (int i = 0; i < 4; i++) {
        lacc[i] += __shfl_xor_sync(0xffffffffu, lacc[i], 1);
        lacc[i] += __shfl_xor_sync(0xffffffffu, lacc[i], 2);
    }
    #pragma unroll
    for (int mt = 0; mt < 2; mt++) {
        int rbase = q0 + w*32 + mt*16;
        float inv0 = 1.f / lacc[mt*2 + 0];
        float inv1 = 1.f / lacc[mt*2 + 1];
        #pragma unroll
        for (int dj = 0; dj < 4; dj++) {
            int col = hoff + dj*8 + 2*tc;
            *(float2*)&Og[(rbase + g    )*CC + col] =
                make_float2(oacc[mt][dj][0]*inv0, oacc[mt][dj][1]*inv0);
            *(float2*)&Og[(rbase + g + 8)*CC + col] =
                make_float2(oacc[mt][dj][2]*inv1, oacc[mt][dj][3]*inv1);
        }
    }
}

// ---------------- small kernels ----------------
__global__ void lin1_kernel(const float* __restrict__ x, const float* __restrict__ w,
                            const float* __restrict__ b) {
    int n = blockIdx.x, c = threadIdx.x;
    g_h[n*CC + c] = x[n]*w[c] + b[c];
}

__global__ void zero_kernel(float* __restrict__ p, int n) {
    int i = blockIdx.x*blockDim.x + threadIdx.x;
    if (i < n) p[i] = 0.f;
}

__global__ void zero_stats_kernel() {
    int i = blockIdx.x*256 + threadIdx.x;
    g_sum[i] = 0.f;
    g_sumsq[i] = 0.f;
}

__global__ void scatter_kernel(const int* __restrict__ ei, int E) {
    const int* src = ei;
    const int* dst = ei + E;
    int c = threadIdx.x;
    int e0 = blockIdx.x * 4;
    #pragma unroll
    for (int k = 0; k < 4; k++) {
        int e = e0 + k;
        int s = src[e], d = dst[e];
        atomicAdd(&g_agg[d*CC + c], g_h[s*CC + c]);
    }
}

// out = BN(in1)*g + b (+ addend); stats from g_sum/g_sumsq at statoff
__global__ void bn_apply_kernel(const float* __restrict__ in1, int statoff,
                                const float* __restrict__ gamma, const float* __restrict__ beta,
                                const float* __restrict__ addend, float* __restrict__ out) {
    int i = blockIdx.x*256 + threadIdx.x;
    int c = i & (CC-1);
    float mean = g_sum[statoff + c] * (1.f/NN);
    float var  = g_sumsq[statoff + c] * (1.f/NN) - mean*mean;
    float r = (in1[i] - mean) * rsqrtf(var + EPSV) * gamma[c] + beta[c];
    if (addend) r += addend[i];
    out[i] = r;
}

// ---------------- host ----------------
extern "C" void kernel_launch(void* const* d_in, const int* in_sizes, int n_in,
                              void* d_out, int out_size) {
    const float* x      = (const float*)d_in[0];
    const int*   ei     = (const int*)  d_in[1];
    const float* lin1_w = (const float*)d_in[2];
    const float* lin1_b = (const float*)d_in[3];
    const float* gin_b1 = (const float*)d_in[5];
    const float* gin_b2 = (const float*)d_in[7];
    const float* bq = (const float*)d_in[12];
    const float* bk = (const float*)d_in[13];
    const float* bv = (const float*)d_in[14];
    const float* bo = (const float*)d_in[15];
    const float* bn1_g = (const float*)d_in[16];
    const float* bn1_b = (const float*)d_in[17];
    const float* bn2_g = (const float*)d_in[18];
    const float* bn2_b = (const float*)d_in[19];
    const float* bn3_g = (const float*)d_in[20];
    const float* bn3_b = (const float*)d_in[21];
    const float* mb1 = (const float*)d_in[23];
    const float* mb2 = (const float*)d_in[25];
    int E = in_sizes[1] / 2;

    float *h, *agg, *t1, *t2, *q, *k, *v, *o, *h1;
    cudaGetSymbolAddress((void**)&h,   g_h);
    cudaGetSymbolAddress((void**)&agg, g_agg);
    cudaGetSymbolAddress((void**)&t1,  g_t1);
    cudaGetSymbolAddress((void**)&t2,  g_t2);
    cudaGetSymbolAddress((void**)&q,   g_q);
    cudaGetSymbolAddress((void**)&k,   g_k);
    cudaGetSymbolAddress((void**)&v,   g_v);
    cudaGetSymbolAddress((void**)&o,   g_o);
    cudaGetSymbolAddress((void**)&h1,  g_h1);
    __half *wh, *wl;
    cudaGetSymbolAddress((void**)&wh, g_wh);
    cudaGetSymbolAddress((void**)&wl, g_wl);

    convw_all_kernel<<<(TOTW + 255)/256, 256>>>(
        (const float*)d_in[4], (const float*)d_in[6],
        (const float*)d_in[8], (const float*)d_in[9],
        (const float*)d_in[10], (const float*)d_in[11],
        (const float*)d_in[22], (const float*)d_in[24]);
    zero_stats_kernel<<<9, 256>>>();

    dim3 gN256(CC/64,   NN/128);
    dim3 gN512(2*CC/64, NN/128);
    dim3 gqkv (CC/64,   NN/128, 3);
    int ewgrid = NN*CC/256;

    lin1_kernel<<<NN, CC>>>(x, lin1_w, lin1_b);

    for (int l = 0; l < LL; l++) {
        int w1 = l*CC*CC, w2 = l*2*CC*CC;
        int so = l*3*CC;
        // ---- GIN branch ----
        zero_kernel<<<ewgrid, 256>>>(agg, NN*CC);
        scatter_kernel<<<E/4, CC>>>(ei, E);
        gemm_mma_kernel<<<gN256, 128>>>(h, agg, wh + OFF_GW1 + w1, wl + OFF_GW1 + w1,
                                        gin_b1 + l*CC, t1, CC, CC, 1, nullptr, -1);
        gemm_mma_kernel<<<gN256, 128>>>(t1, nullptr, wh + OFF_GW2 + w1, wl + OFF_GW2 + w1,
                                        gin_b2 + l*CC, t2, CC, CC, 0, h, so);
        bn_apply_kernel<<<ewgrid, 256>>>(t2, so, bn1_g + l*CC, bn1_b + l*CC, nullptr, h1);
        // ---- attention branch ----
        qkv_mma_kernel<<<gqkv, 128>>>(h, wh, wl, bq + l*CC, bk + l*CC, bv + l*CC, q, k, v, l);
        flash_mma_kernel<<<dim3(NN/256, HH), 256>>>(q, k, v, o);
        gemm_mma_kernel<<<gN256, 128>>>(o, nullptr, wh + OFF_WO + w1, wl + OFF_WO + w1,
                                        bo + l*CC, k /*reused*/, CC, CC, 0, h, so + CC);
        bn_apply_kernel<<<ewgrid, 256>>>(k, so + CC, bn2_g + l*CC, bn2_b + l*CC, h1, q);
        // ---- feedforward ----
        gemm_mma_kernel<<<gN512, 128>>>(q, nullptr, wh + OFF_MW1 + w2, wl + OFF_MW1 + w2,
                                        mb1 + l*2*CC, t1, 2*CC, CC, 1, nullptr, -1);
        gemm_mma_kernel<<<gN256, 128>>>(t1, nullptr, wh + OFF_MW2 + w2, wl + OFF_MW2 + w2,
                                        mb2 + l*CC, t2, CC, 2*CC, 0, q, so + 2*CC);
        bn_apply_kernel<<<ewgrid, 256>>>(t2, so + 2*CC, bn3_g + l*CC, bn3_b + l*CC, nullptr,
                                         (l == LL-1) ? (float*)d_out : h);
    }
    (void)n_in; (void)out_size;
}

// round 12
// speedup vs baseline: 1.0891x; 1.0891x over previous
#include <cuda_runtime.h>
#include <cuda_fp16.h>
#include <math.h>
#include <stdint.h>

#define NN 4096
#define CC 256
#define HH 8
#define DHH 32
#define LL 3
#define EPSV 1e-5f
#define QSC (0.17677669529663687f * 1.4426950408889634f)

// ---------------- scratch (no allocation allowed) ----------------
__device__ float g_h[NN*CC];
__device__ float g_agg[NN*CC];
__device__ float g_t1[NN*2*CC];
__device__ float g_t2[NN*CC];
__device__ float g_q[NN*CC];
__device__ float g_k[NN*CC];
__device__ float g_v[NN*CC];
__device__ float g_o[NN*CC];
__device__ float g_h1[NN*CC];
__device__ float g_sum[9*CC];     // one set per BN instance
__device__ float g_sumsq[9*CC];

// fp16 hi/lo weight cache (converted each launch; deterministic)
#define OFF_GW1 0
#define OFF_GW2 196608
#define OFF_WQ  393216
#define OFF_WK  589824
#define OFF_WV  786432
#define OFF_WO  983040
#define OFF_MW1 1179648
#define OFF_MW2 1572864
#define TOTW    1966080
__device__ __half g_wh[TOTW];
__device__ __half g_wl[TOTW];

// ---------------- mma helpers ----------------
__device__ __forceinline__ void mma16816(float* d, const uint32_t* a, const uint32_t* b) {
    asm volatile(
        "mma.sync.aligned.m16n8k16.row.col.f32.f16.f16.f32 "
        "{%0,%1,%2,%3}, {%4,%5,%6,%7}, {%8,%9}, {%0,%1,%2,%3};"
        : "+f"(d[0]), "+f"(d[1]), "+f"(d[2]), "+f"(d[3])
        : "r"(a[0]), "r"(a[1]), "r"(a[2]), "r"(a[3]), "r"(b[0]), "r"(b[1]));
}
__device__ __forceinline__ uint32_t packh2(float x, float y) {
    __half2 h = __floats2half2_rn(x, y);
    return *(uint32_t*)&h;
}

// ---------------- weight conversion: all 8 regions, one launch ----------------
__global__ void convw_all_kernel(
    const float* __restrict__ gw1, const float* __restrict__ gw2,
    const float* __restrict__ wq,  const float* __restrict__ wk,
    const float* __restrict__ wv,  const float* __restrict__ wo,
    const float* __restrict__ mw1, const float* __restrict__ mw2)
{
    int i = blockIdx.x*256 + threadIdx.x;
    if (i >= TOTW) return;
    const float* src; int off;
    if      (i < OFF_GW2) { src = gw1; off = OFF_GW1; }
    else if (i < OFF_WQ)  { src = gw2; off = OFF_GW2; }
    else if (i < OFF_WK)  { src = wq;  off = OFF_WQ;  }
    else if (i < OFF_WV)  { src = wk;  off = OFF_WK;  }
    else if (i < OFF_WO)  { src = wv;  off = OFF_WV;  }
    else if (i < OFF_MW1) { src = wo;  off = OFF_WO;  }
    else if (i < OFF_MW2) { src = mw1; off = OFF_MW1; }
    else                  { src = mw2; off = OFF_MW2; }
    float x = src[i - off];
    __half h = __float2half_rn(x);
    g_wh[i] = h;
    g_wl[i] = __float2half_rn(x - __half2float(h));
}

// ---------------- HMMA GEMM (3-term hi/lo split), plain epilogue ----------------
#define APAD 40
__device__ __forceinline__ void gemm_mma_body(
    const float* __restrict__ A1, const float* __restrict__ A2,
    const __half* __restrict__ Bh, const __half* __restrict__ Bl,
    const float* __restrict__ bias, float* __restrict__ C,
    int Nout, int K, int relu, int m0, int n0)
{
    __shared__ __half Ah[128][APAD];
    __shared__ __half Al[128][APAD];
    __shared__ __half Bhs[64][APAD];
    __shared__ __half Bls[64][APAD];

    const int tid = threadIdx.x;
    const int w = tid >> 5, lane = tid & 31;
    const int g = lane >> 2, tc = lane & 3;
    const int wm = w & 1, wn = w >> 1;

    float acc[4][4][4] = {};

    for (int k0 = 0; k0 < K; k0 += 32) {
        #pragma unroll
        for (int it = 0; it < 16; it++) {
            int idx = it*128 + tid;
            int r = idx >> 4, c2 = idx & 15;
            const float* p = &A1[(m0 + r)*K + k0 + c2*2];
            float ax = p[0], ay = p[1];
            if (A2) { const float* p2 = &A2[(m0 + r)*K + k0 + c2*2]; ax += p2[0]; ay += p2[1]; }
            __half hx = __float2half_rn(ax), hy = __float2half_rn(ay);
            Ah[r][c2*2]   = hx; Ah[r][c2*2+1] = hy;
            Al[r][c2*2]   = __float2half_rn(ax - __half2float(hx));
            Al[r][c2*2+1] = __float2half_rn(ay - __half2float(hy));
        }
        #pragma unroll
        for (int it = 0; it < 8; it++) {
            int idx = it*128 + tid;
            int r = idx >> 4, c2 = idx & 15;
            *(__half2*)&Bhs[r][c2*2] = *(const __half2*)&Bh[(n0 + r)*K + k0 + c2*2];
            *(__half2*)&Bls[r][c2*2] = *(const __half2*)&Bl[(n0 + r)*K + k0 + c2*2];
        }
        __syncthreads();

        #pragma unroll
        for (int kt = 0; kt < 2; kt++) {
            uint32_t ah[4][4], al[4][4], bh[4][2], bl[4][2];
            #pragma unroll
            for (int mt = 0; mt < 4; mt++) {
                int rb = wm*64 + mt*16 + g;
                int c = kt*16 + 2*tc;
                ah[mt][0] = *(const uint32_t*)&Ah[rb    ][c];
                ah[mt][1] = *(const uint32_t*)&Ah[rb + 8][c];
                ah[mt][2] = *(const uint32_t*)&Ah[rb    ][c + 8];
                ah[mt][3] = *(const uint32_t*)&Ah[rb + 8][c + 8];
                al[mt][0] = *(const uint32_t*)&Al[rb    ][c];
                al[mt][1] = *(const uint32_t*)&Al[rb + 8][c];
                al[mt][2] = *(const uint32_t*)&Al[rb    ][c + 8];
                al[mt][3] = *(const uint32_t*)&Al[rb + 8][c + 8];
            }
            #pragma unroll
            for (int nt = 0; nt < 4; nt++) {
                int nb = wn*32 + nt*8 + g;
                int c = kt*16 + 2*tc;
                bh[nt][0] = *(const uint32_t*)&Bhs[nb][c];
                bh[nt][1] = *(const uint32_t*)&Bhs[nb][c + 8];
                bl[nt][0] = *(const uint32_t*)&Bls[nb][c];
                bl[nt][1] = *(const uint32_t*)&Bls[nb][c + 8];
            }
            #pragma unroll
            for (int mt = 0; mt < 4; mt++)
                #pragma unroll
                for (int nt = 0; nt < 4; nt++) {
                    mma16816(acc[mt][nt], ah[mt], bh[nt]);
                    mma16816(acc[mt][nt], al[mt], bh[nt]);
                    mma16816(acc[mt][nt], ah[mt], bl[nt]);
                }
        }
        __syncthreads();
    }

    #pragma unroll
    for (int mt = 0; mt < 4; mt++) {
        int row = m0 + wm*64 + mt*16 + g;
        #pragma unroll
        for (int nt = 0; nt < 4; nt++) {
            int col = n0 + wn*32 + nt*8 + 2*tc;
            float b0 = bias[col], b1 = bias[col + 1];
            float v0 = acc[mt][nt][0] + b0, v1 = acc[mt][nt][1] + b1;
            float v2 = acc[mt][nt][2] + b0, v3 = acc[mt][nt][3] + b1;
            if (relu) {
                v0 = fmaxf(v0, 0.f); v1 = fmaxf(v1, 0.f);
                v2 = fmaxf(v2, 0.f); v3 = fmaxf(v3, 0.f);
            }
            *(float2*)&C[row*Nout + col]       = make_float2(v0, v1);
            *(float2*)&C[(row + 8)*Nout + col] = make_float2(v2, v3);
        }
    }
}

__global__ void __launch_bounds__(128) gemm_mma_kernel(
    const float* __restrict__ A1, const float* __restrict__ A2,
    const __half* __restrict__ Bh, const __half* __restrict__ Bl,
    const float* __restrict__ bias, float* __restrict__ C,
    int Nout, int K, int relu)
{
    gemm_mma_body(A1, A2, Bh, Bl, bias, C, Nout, K, relu,
                  blockIdx.y*128, blockIdx.x*64);
}

__global__ void __launch_bounds__(128) qkv_mma_kernel(
    const float* __restrict__ A, const __half* __restrict__ wh,
    const __half* __restrict__ wl,
    const float* __restrict__ bq, const float* __restrict__ bk,
    const float* __restrict__ bv,
    float* __restrict__ q, float* __restrict__ k, float* __restrict__ v, int l)
{
    const __half *Bh, *Bl; const float* bias; float* C;
    int woff = l*CC*CC;
    if (blockIdx.z == 0)      { Bh = wh + OFF_WQ + woff; Bl = wl + OFF_WQ + woff; bias = bq; C = q; }
    else if (blockIdx.z == 1) { Bh = wh + OFF_WK + woff; Bl = wl + OFF_WK + woff; bias = bk; C = k; }
    else                      { Bh = wh + OFF_WV + woff; Bl = wl + OFF_WV + woff; bias = bv; C = v; }
    gemm_mma_body(A, nullptr, Bh, Bl, bias, C, CC, CC, 0,
                  blockIdx.y*128, blockIdx.x*64);
}

// ---------------- flash attention (fp16 mma, online softmax, skip-rescale) ----------------
#define QPAD 36
#define VPAD 132
__global__ void __launch_bounds__(256) flash_mma_kernel(
    const float* __restrict__ Q, const float* __restrict__ Kp,
    const float* __restrict__ V, float* __restrict__ Og)
{
    __shared__ __half Qs[256][QPAD];
    __shared__ __half Ks[128][QPAD];
    __shared__ __half VTs[32][VPAD];

    const int tid = threadIdx.x;
    const int w = tid >> 5, lane = tid & 31;
    const int g = lane >> 2, tc = lane & 3;
    const int hoff = blockIdx.y * DHH;
    const int q0 = blockIdx.x * 256;

    #pragma unroll
    for (int it = 0; it < 16; it++) {
        int idx = it*256 + tid;
        int r = idx >> 4, pr = idx & 15;
        float2 f = *(const float2*)&Q[(q0 + r)*CC + hoff + pr*2];
        *(__half2*)&Qs[r][pr*2] = __floats2half2_rn(f.x * QSC, f.y * QSC);
    }
    __syncthreads();

    uint32_t qa[2][2][4];
    #pragma unroll
    for (int mt = 0; mt < 2; mt++) {
        #pragma unroll
        for (int kt = 0; kt < 2; kt++) {
            int r0 = w*32 + mt*16 + g;
            qa[mt][kt][0] = *(const uint32_t*)&Qs[r0    ][kt*16 + 2*tc    ];
            qa[mt][kt][1] = *(const uint32_t*)&Qs[r0 + 8][kt*16 + 2*tc    ];
            qa[mt][kt][2] = *(const uint32_t*)&Qs[r0    ][kt*16 + 2*tc + 8];
            qa[mt][kt][3] = *(const uint32_t*)&Qs[r0 + 8][kt*16 + 2*tc + 8];
        }
    }

    float oacc[2][4][4] = {};
    float lacc[4] = {};
    float mrow[4] = {-1e30f, -1e30f, -1e30f, -1e30f};

    for (int j0 = 0; j0 < NN; j0 += 128) {
        __syncthreads();
        #pragma unroll
        for (int it = 0; it < 8; it++) {
            int idx = it*256 + tid;
            int r = idx >> 4, pr = idx & 15;
            float2 f = *(const float2*)&Kp[(j0 + r)*CC + hoff + pr*2];
            *(__half2*)&Ks[r][pr*2] = __floats2half2_rn(f.x, f.y);
        }
        #pragma unroll
        for (int it = 0; it < 8; it++) {
            int idx = it*256 + tid;
            int j = idx >> 4, dp = idx & 15;
            float2 f = *(const float2*)&V[(j0 + j)*CC + hoff + dp*2];
            VTs[dp*2    ][j] = __float2half(f.x);
            VTs[dp*2 + 1][j] = __float2half(f.y);
        }
        __syncthreads();

        #pragma unroll
        for (int ng = 0; ng < 8; ng++) {
            const int kb = ng*16;
            float s[2][2][4] = {};
            #pragma unroll
            for (int kt = 0; kt < 2; kt++) {
                uint32_t b[2][2];
                #pragma unroll
                for (int j = 0; j < 2; j++) {
                    int key = kb + j*8 + g;
                    b[j][0] = *(const uint32_t*)&Ks[key][kt*16 + 2*tc    ];
                    b[j][1] = *(const uint32_t*)&Ks[key][kt*16 + 2*tc + 8];
                }
                #pragma unroll
                for (int mt = 0; mt < 2; mt++)
                    #pragma unroll
                    for (int j = 0; j < 2; j++)
                        mma16816(s[mt][j], qa[mt][kt], b[j]);
            }
            uint32_t pa[2][4];
            #pragma unroll
            for (int mt = 0; mt < 2; mt++) {
                #pragma unroll
                for (int hi = 0; hi < 2; hi++) {
                    float rm = fmaxf(fmaxf(s[mt][0][2*hi], s[mt][0][2*hi+1]),
                                     fmaxf(s[mt][1][2*hi], s[mt][1][2*hi+1]));
                    rm = fmaxf(rm, __shfl_xor_sync(0xffffffffu, rm, 1));
                    rm = fmaxf(rm, __shfl_xor_sync(0xffffffffu, rm, 2));
                    float mold = mrow[mt*2 + hi];
                    float mnew = fmaxf(mold, rm);
                    float p00 = exp2f(s[mt][0][2*hi]   - mnew);
                    float p01 = exp2f(s[mt][0][2*hi+1] - mnew);
                    float p10 = exp2f(s[mt][1][2*hi]   - mnew);
                    float p11 = exp2f(s[mt][1][2*hi+1] - mnew);
                    float psum = p00 + p01 + p10 + p11;
                    if (rm > mold) {
                        float cf = exp2f(mold - mnew);
                        mrow[mt*2 + hi] = mnew;
                        lacc[mt*2 + hi] = lacc[mt*2 + hi]*cf + psum;
                        #pragma unroll
                        for (int dj = 0; dj < 4; dj++) {
                            oacc[mt][dj][2*hi]   *= cf;
                            oacc[mt][dj][2*hi+1] *= cf;
                        }
                    } else {
                        lacc[mt*2 + hi] += psum;
                    }
                    pa[mt][0*2 + hi] = packh2(p00, p01);
                    pa[mt][1*2 + hi] = packh2(p10, p11);
                }
            }
            #pragma unroll
            for (int dj = 0; dj < 4; dj++) {
                uint32_t vb[2];
                vb[0] = *(const uint32_t*)&VTs[dj*8 + g][kb + 2*tc    ];
                vb[1] = *(const uint32_t*)&VTs[dj*8 + g][kb + 2*tc + 8];
                #pragma unroll
                for (int mt = 0; mt < 2; mt++)
                    mma16816(oacc[mt][dj], pa[mt], vb);
            }
        }
    }

    #pragma unroll
    for (int i = 0; i < 4; i++) {
        lacc[i] += __shfl_xor_sync(0xffffffffu, lacc[i], 1);
        lacc[i] += __shfl_xor_sync(0xffffffffu, lacc[i], 2);
    }
    #pragma unroll
    for (int mt = 0; mt < 2; mt++) {
        int rbase = q0 + w*32 + mt*16;
        float inv0 = 1.f / lacc[mt*2 + 0];
        float inv1 = 1.f / lacc[mt*2 + 1];
        #pragma unroll
        for (int dj = 0; dj < 4; dj++) {
            int col = hoff + dj*8 + 2*tc;
            *(float2*)&Og[(rbase + g    )*CC + col] =
                make_float2(oacc[mt][dj][0]*inv0, oacc[mt][dj][1]*inv0);
            *(float2*)&Og[(rbase + g + 8)*CC + col] =
                make_float2(oacc[mt][dj][2]*inv1, oacc[mt][dj][3]*inv1);
        }
    }
}

// ---------------- small kernels ----------------
__global__ void lin1_kernel(const float* __restrict__ x, const float* __restrict__ w,
                            const float* __restrict__ b) {
    int n = blockIdx.x, c = threadIdx.x;
    g_h[n*CC + c] = x[n]*w[c] + b[c];
}

__global__ void zero_kernel(float* __restrict__ p, int n) {
    int i = blockIdx.x*blockDim.x + threadIdx.x;
    if (i < n) p[i] = 0.f;
}

__global__ void zero_stats_kernel() {
    int i = blockIdx.x*256 + threadIdx.x;
    g_sum[i] = 0.f;
    g_sumsq[i] = 0.f;
}

__global__ void scatter_kernel(const int* __restrict__ ei, int E) {
    const int* src = ei;
    const int* dst = ei + E;
    int c = threadIdx.x;
    int e0 = blockIdx.x * 4;
    #pragma unroll
    for (int k = 0; k < 4; k++) {
        int e = e0 + k;
        int s = src[e], d = dst[e];
        atomicAdd(&g_agg[d*CC + c], g_h[s*CC + c]);
    }
}

// 128 blocks x 32 rows; accumulate into stats slot statoff
__global__ void bn_stats_kernel(const float* __restrict__ in1, const float* __restrict__ in2,
                                int statoff) {
    int c = threadIdx.x;
    int r0 = blockIdx.x * 32;
    float s = 0.f, ss = 0.f;
    #pragma unroll 4
    for (int r = r0; r < r0 + 32; r++) {
        float v = in1[r*CC + c] + in2[r*CC + c];
        s += v; ss += v*v;
    }
    atomicAdd(&g_sum[statoff + c], s);
    atomicAdd(&g_sumsq[statoff + c], ss);
}

__global__ void bn_apply_kernel(const float* __restrict__ in1, const float* __restrict__ in2,
                                int statoff,
                                const float* __restrict__ gamma, const float* __restrict__ beta,
                                const float* __restrict__ addend, float* __restrict__ out) {
    int i = blockIdx.x*256 + threadIdx.x;
    int c = i & (CC-1);
    float mean = g_sum[statoff + c] * (1.f/NN);
    float var  = g_sumsq[statoff + c] * (1.f/NN) - mean*mean;
    float v = in1[i] + in2[i];
    float r = (v - mean) * rsqrtf(var + EPSV) * gamma[c] + beta[c];
    if (addend) r += addend[i];
    out[i] = r;
}

// ---------------- host ----------------
extern "C" void kernel_launch(void* const* d_in, const int* in_sizes, int n_in,
                              void* d_out, int out_size) {
    const float* x      = (const float*)d_in[0];
    const int*   ei     = (const int*)  d_in[1];
    const float* lin1_w = (const float*)d_in[2];
    const float* lin1_b = (const float*)d_in[3];
    const float* gin_b1 = (const float*)d_in[5];
    const float* gin_b2 = (const float*)d_in[7];
    const float* bq = (const float*)d_in[12];
    const float* bk = (const float*)d_in[13];
    const float* bv = (const float*)d_in[14];
    const float* bo = (const float*)d_in[15];
    const float* bn1_g = (const float*)d_in[16];
    const float* bn1_b = (const float*)d_in[17];
    const float* bn2_g = (const float*)d_in[18];
    const float* bn2_b = (const float*)d_in[19];
    const float* bn3_g = (const float*)d_in[20];
    const float* bn3_b = (const float*)d_in[21];
    const float* mb1 = (const float*)d_in[23];
    const float* mb2 = (const float*)d_in[25];
    int E = in_sizes[1] / 2;

    float *h, *agg, *t1, *t2, *q, *k, *v, *o, *h1;
    cudaGetSymbolAddress((void**)&h,   g_h);
    cudaGetSymbolAddress((void**)&agg, g_agg);
    cudaGetSymbolAddress((void**)&t1,  g_t1);
    cudaGetSymbolAddress((void**)&t2,  g_t2);
    cudaGetSymbolAddress((void**)&q,   g_q);
    cudaGetSymbolAddress((void**)&k,   g_k);
    cudaGetSymbolAddress((void**)&v,   g_v);
    cudaGetSymbolAddress((void**)&o,   g_o);
    cudaGetSymbolAddress((void**)&h1,  g_h1);
    __half *wh, *wl;
    cudaGetSymbolAddress((void**)&wh, g_wh);
    cudaGetSymbolAddress((void**)&wl, g_wl);

    convw_all_kernel<<<(TOTW + 255)/256, 256>>>(
        (const float*)d_in[4], (const float*)d_in[6],
        (const float*)d_in[8], (const float*)d_in[9],
        (const float*)d_in[10], (const float*)d_in[11],
        (const float*)d_in[22], (const float*)d_in[24]);
    zero_stats_kernel<<<9, 256>>>();

    dim3 gN256(CC/64,   NN/128);
    dim3 gN512(2*CC/64, NN/128);
    dim3 gqkv (CC/64,   NN/128, 3);
    int ewgrid = NN*CC/256;

    lin1_kernel<<<NN, CC>>>(x, lin1_w, lin1_b);

    for (int l = 0; l < LL; l++) {
        int w1 = l*CC*CC, w2 = l*2*CC*CC;
        int so = l*3*CC;
        // ---- GIN branch ----
        zero_kernel<<<ewgrid, 256>>>(agg, NN*CC);
        scatter_kernel<<<E/4, CC>>>(ei, E);
        gemm_mma_kernel<<<gN256, 128>>>(h, agg, wh + OFF_GW1 + w1, wl + OFF_GW1 + w1,
                                        gin_b1 + l*CC, t1, CC, CC, 1);
        gemm_mma_kernel<<<gN256, 128>>>(t1, nullptr, wh + OFF_GW2 + w1, wl + OFF_GW2 + w1,
                                        gin_b2 + l*CC, t2, CC, CC, 0);
        bn_stats_kernel<<<128, CC>>>(t2, h, so);
        bn_apply_kernel<<<ewgrid, 256>>>(t2, h, so, bn1_g + l*CC, bn1_b + l*CC, nullptr, h1);
        // ---- global attention ----
        qkv_mma_kernel<<<gqkv, 128>>>(h, wh, wl, bq + l*CC, bk + l*CC, bv + l*CC, q, k, v, l);
        flash_mma_kernel<<<dim3(NN/256, HH), 256>>>(q, k, v, o);
        gemm_mma_kernel<<<gN256, 128>>>(o, nullptr, wh + OFF_WO + w1, wl + OFF_WO + w1,
                                        bo + l*CC, t2, CC, CC, 0);
        bn_stats_kernel<<<128, CC>>>(t2, h, so + CC);
        bn_apply_kernel<<<ewgrid, 256>>>(t2, h, so + CC, bn2_g + l*CC, bn2_b + l*CC, h1, q);
        // ---- feedforward ----
        gemm_mma_kernel<<<gN512, 128>>>(q, nullptr, wh + OFF_MW1 + w2, wl + OFF_MW1 + w2,
                                        mb1 + l*2*CC, t1, 2*CC, CC, 1);
        gemm_mma_kernel<<<gN256, 128>>>(t1, nullptr, wh + OFF_MW2 + w2, wl + OFF_MW2 + w2,
                                        mb2 + l*CC, t2, CC, 2*CC, 0);
        bn_stats_kernel<<<128, CC>>>(t2, q, so + 2*CC);
        bn_apply_kernel<<<ewgrid, 256>>>(t2, q, so + 2*CC, bn3_g + l*CC, bn3_b + l*CC, nullptr,
                                         (l == LL-1) ? (float*)d_out : h);
    }
    (void)n_in; (void)out_size;
}

// round 13
// speedup vs baseline: 1.0955x; 1.0059x over previous
#include <cuda_runtime.h>
#include <cuda_fp16.h>
#include <math.h>
#include <stdint.h>

#define NN 4096
#define CC 256
#define HH 8
#define DHH 32
#define LL 3
#define EPSV 1e-5f
#define QSC (0.17677669529663687f * 1.4426950408889634f)

// ---------------- scratch (no allocation allowed) ----------------
__device__ float g_h[NN*CC];
__device__ float g_agg[NN*CC];
__device__ float g_t1[NN*2*CC];
__device__ float g_t2[NN*CC];
__device__ float g_q[NN*CC];      // fp32 reuse buffer (bn2 output, ffn input)
__device__ float g_t3[NN*CC];
__device__ float g_o[NN*CC];
__device__ float g_h1[NN*CC];
__device__ __half g_qh[NN*CC];    // fp16 q/k/v for flash
__device__ __half g_kh[NN*CC];
__device__ __half g_vh[NN*CC];
__device__ float g_sum[9*CC];
__device__ float g_sumsq[9*CC];

// fp16 hi/lo weight cache
#define OFF_GW1 0
#define OFF_GW2 196608
#define OFF_WQ  393216
#define OFF_WK  589824
#define OFF_WV  786432
#define OFF_WO  983040
#define OFF_MW1 1179648
#define OFF_MW2 1572864
#define TOTW    1966080
__device__ __half g_wh[TOTW];
__device__ __half g_wl[TOTW];

// ---------------- mma helpers ----------------
__device__ __forceinline__ void mma16816(float* d, const uint32_t* a, const uint32_t* b) {
    asm volatile(
        "mma.sync.aligned.m16n8k16.row.col.f32.f16.f16.f32 "
        "{%0,%1,%2,%3}, {%4,%5,%6,%7}, {%8,%9}, {%0,%1,%2,%3};"
        : "+f"(d[0]), "+f"(d[1]), "+f"(d[2]), "+f"(d[3])
        : "r"(a[0]), "r"(a[1]), "r"(a[2]), "r"(a[3]), "r"(b[0]), "r"(b[1]));
}
__device__ __forceinline__ uint32_t packh2(float x, float y) {
    __half2 h = __floats2half2_rn(x, y);
    return *(uint32_t*)&h;
}

// ---------------- weight conversion: all 8 regions, one launch ----------------
__global__ void convw_all_kernel(
    const float* __restrict__ gw1, const float* __restrict__ gw2,
    const float* __restrict__ wq,  const float* __restrict__ wk,
    const float* __restrict__ wv,  const float* __restrict__ wo,
    const float* __restrict__ mw1, const float* __restrict__ mw2)
{
    int i = blockIdx.x*256 + threadIdx.x;
    if (i >= TOTW) return;
    const float* src; int off;
    if      (i < OFF_GW2) { src = gw1; off = OFF_GW1; }
    else if (i < OFF_WQ)  { src = gw2; off = OFF_GW2; }
    else if (i < OFF_WK)  { src = wq;  off = OFF_WQ;  }
    else if (i < OFF_WV)  { src = wk;  off = OFF_WK;  }
    else if (i < OFF_WO)  { src = wv;  off = OFF_WV;  }
    else if (i < OFF_MW1) { src = wo;  off = OFF_WO;  }
    else if (i < OFF_MW2) { src = mw1; off = OFF_MW1; }
    else                  { src = mw2; off = OFF_MW2; }
    float x = src[i - off];
    __half h = __float2half_rn(x);
    g_wh[i] = h;
    g_wl[i] = __float2half_rn(x - __half2float(h));
}

// ---------------- HMMA GEMM (3-term hi/lo split); OUTHALF selects fp16 output ----------------
#define APAD 40
template<bool OUTHALF>
__device__ __forceinline__ void gemm_mma_body(
    const float* __restrict__ A1, const float* __restrict__ A2,
    const __half* __restrict__ Bh, const __half* __restrict__ Bl,
    const float* __restrict__ bias, void* __restrict__ Cv,
    int Nout, int K, int relu, int m0, int n0)
{
    __shared__ __half Ah[128][APAD];
    __shared__ __half Al[128][APAD];
    __shared__ __half Bhs[64][APAD];
    __shared__ __half Bls[64][APAD];

    const int tid = threadIdx.x;
    const int w = tid >> 5, lane = tid & 31;
    const int g = lane >> 2, tc = lane & 3;
    const int wm = w & 1, wn = w >> 1;

    float acc[4][4][4] = {};

    for (int k0 = 0; k0 < K; k0 += 32) {
        #pragma unroll
        for (int it = 0; it < 16; it++) {
            int idx = it*128 + tid;
            int r = idx >> 4, c2 = idx & 15;
            const float* p = &A1[(m0 + r)*K + k0 + c2*2];
            float ax = p[0], ay = p[1];
            if (A2) { const float* p2 = &A2[(m0 + r)*K + k0 + c2*2]; ax += p2[0]; ay += p2[1]; }
            __half hx = __float2half_rn(ax), hy = __float2half_rn(ay);
            Ah[r][c2*2]   = hx; Ah[r][c2*2+1] = hy;
            Al[r][c2*2]   = __float2half_rn(ax - __half2float(hx));
            Al[r][c2*2+1] = __float2half_rn(ay - __half2float(hy));
        }
        #pragma unroll
        for (int it = 0; it < 8; it++) {
            int idx = it*128 + tid;
            int r = idx >> 4, c2 = idx & 15;
            *(__half2*)&Bhs[r][c2*2] = *(const __half2*)&Bh[(n0 + r)*K + k0 + c2*2];
            *(__half2*)&Bls[r][c2*2] = *(const __half2*)&Bl[(n0 + r)*K + k0 + c2*2];
        }
        __syncthreads();

        #pragma unroll
        for (int kt = 0; kt < 2; kt++) {
            uint32_t ah[4][4], al[4][4], bh[4][2], bl[4][2];
            #pragma unroll
            for (int mt = 0; mt < 4; mt++) {
                int rb = wm*64 + mt*16 + g;
                int c = kt*16 + 2*tc;
                ah[mt][0] = *(const uint32_t*)&Ah[rb    ][c];
                ah[mt][1] = *(const uint32_t*)&Ah[rb + 8][c];
                ah[mt][2] = *(const uint32_t*)&Ah[rb    ][c + 8];
                ah[mt][3] = *(const uint32_t*)&Ah[rb + 8][c + 8];
                al[mt][0] = *(const uint32_t*)&Al[rb    ][c];
                al[mt][1] = *(const uint32_t*)&Al[rb + 8][c];
                al[mt][2] = *(const uint32_t*)&Al[rb    ][c + 8];
                al[mt][3] = *(const uint32_t*)&Al[rb + 8][c + 8];
            }
            #pragma unroll
            for (int nt = 0; nt < 4; nt++) {
                int nb = wn*32 + nt*8 + g;
                int c = kt*16 + 2*tc;
                bh[nt][0] = *(const uint32_t*)&Bhs[nb][c];
                bh[nt][1] = *(const uint32_t*)&Bhs[nb][c + 8];
                bl[nt][0] = *(const uint32_t*)&Bls[nb][c];
                bl[nt][1] = *(const uint32_t*)&Bls[nb][c + 8];
            }
            #pragma unroll
            for (int mt = 0; mt < 4; mt++)
                #pragma unroll
                for (int nt = 0; nt < 4; nt++) {
                    mma16816(acc[mt][nt], ah[mt], bh[nt]);
                    mma16816(acc[mt][nt], al[mt], bh[nt]);
                    mma16816(acc[mt][nt], ah[mt], bl[nt]);
                }
        }
        __syncthreads();
    }

    #pragma unroll
    for (int mt = 0; mt < 4; mt++) {
        int row = m0 + wm*64 + mt*16 + g;
        #pragma unroll
        for (int nt = 0; nt < 4; nt++) {
            int col = n0 + wn*32 + nt*8 + 2*tc;
            float b0 = bias[col], b1 = bias[col + 1];
            float v0 = acc[mt][nt][0] + b0, v1 = acc[mt][nt][1] + b1;
            float v2 = acc[mt][nt][2] + b0, v3 = acc[mt][nt][3] + b1;
            if (relu) {
                v0 = fmaxf(v0, 0.f); v1 = fmaxf(v1, 0.f);
                v2 = fmaxf(v2, 0.f); v3 = fmaxf(v3, 0.f);
            }
            if (OUTHALF) {
                __half* C = (__half*)Cv;
                *(__half2*)&C[row*Nout + col]       = __floats2half2_rn(v0, v1);
                *(__half2*)&C[(row + 8)*Nout + col] = __floats2half2_rn(v2, v3);
            } else {
                float* C = (float*)Cv;
                *(float2*)&C[row*Nout + col]       = make_float2(v0, v1);
                *(float2*)&C[(row + 8)*Nout + col] = make_float2(v2, v3);
            }
        }
    }
}

__global__ void __launch_bounds__(128) gemm_mma_kernel(
    const float* __restrict__ A1, const float* __restrict__ A2,
    const __half* __restrict__ Bh, const __half* __restrict__ Bl,
    const float* __restrict__ bias, float* __restrict__ C,
    int Nout, int K, int relu)
{
    gemm_mma_body<false>(A1, A2, Bh, Bl, bias, C, Nout, K, relu,
                         blockIdx.y*128, blockIdx.x*64);
}

// fused Q/K/V projection, fp16 output
__global__ void __launch_bounds__(128) qkv_mma_kernel(
    const float* __restrict__ A, const __half* __restrict__ wh,
    const __half* __restrict__ wl,
    const float* __restrict__ bq, const float* __restrict__ bk,
    const float* __restrict__ bv, int l)
{
    const __half *Bh, *Bl; const float* bias; __half* C;
    int woff = l*CC*CC;
    if (blockIdx.z == 0)      { Bh = wh + OFF_WQ + woff; Bl = wl + OFF_WQ + woff; bias = bq; C = g_qh; }
    else if (blockIdx.z == 1) { Bh = wh + OFF_WK + woff; Bl = wl + OFF_WK + woff; bias = bk; C = g_kh; }
    else                      { Bh = wh + OFF_WV + woff; Bl = wl + OFF_WV + woff; bias = bv; C = g_vh; }
    gemm_mma_body<true>(A, nullptr, Bh, Bl, bias, C, CC, CC, 0,
                        blockIdx.y*128, blockIdx.x*64);
}

// ---------------- flash attention (fp16 in gmem, fp16 mma, online softmax) ----------------
#define QPAD 36
#define VPAD 132
__global__ void __launch_bounds__(256) flash_mma_kernel(
    const __half* __restrict__ Q, const __half* __restrict__ Kp,
    const __half* __restrict__ V, float* __restrict__ Og)
{
    __shared__ __half Qs[256][QPAD];
    __shared__ __half Ks[128][QPAD];
    __shared__ __half VTs[32][VPAD];

    const int tid = threadIdx.x;
    const int w = tid >> 5, lane = tid & 31;
    const int g = lane >> 2, tc = lane & 3;
    const int hoff = blockIdx.y * DHH;
    const int q0 = blockIdx.x * 256;
    const __half2 qsc2 = __float2half2_rn(QSC);

    #pragma unroll
    for (int it = 0; it < 16; it++) {
        int idx = it*256 + tid;
        int r = idx >> 4, pr = idx & 15;
        __half2 h2 = *(const __half2*)&Q[(q0 + r)*CC + hoff + pr*2];
        *(__half2*)&Qs[r][pr*2] = __hmul2(h2, qsc2);
    }
    __syncthreads();

    uint32_t qa[2][2][4];
    #pragma unroll
    for (int mt = 0; mt < 2; mt++) {
        #pragma unroll
        for (int kt = 0; kt < 2; kt++) {
            int r0 = w*32 + mt*16 + g;
            qa[mt][kt][0] = *(const uint32_t*)&Qs[r0    ][kt*16 + 2*tc    ];
            qa[mt][kt][1] = *(const uint32_t*)&Qs[r0 + 8][kt*16 + 2*tc    ];
            qa[mt][kt][2] = *(const uint32_t*)&Qs[r0    ][kt*16 + 2*tc + 8];
            qa[mt][kt][3] = *(const uint32_t*)&Qs[r0 + 8][kt*16 + 2*tc + 8];
        }
    }

    float oacc[2][4][4] = {};
    float lacc[4] = {};
    float mrow[4] = {-1e30f, -1e30f, -1e30f, -1e30f};

    for (int j0 = 0; j0 < NN; j0 += 128) {
        __syncthreads();
        #pragma unroll
        for (int it = 0; it < 8; it++) {
            int idx = it*256 + tid;
            int r = idx >> 4, pr = idx & 15;
            *(uint32_t*)&Ks[r][pr*2] = *(const uint32_t*)&Kp[(j0 + r)*CC + hoff + pr*2];
        }
        #pragma unroll
        for (int it = 0; it < 8; it++) {
            int idx = it*256 + tid;
            int j = idx >> 4, dp = idx & 15;
            __half2 h2 = *(const __half2*)&V[(j0 + j)*CC + hoff + dp*2];
            VTs[dp*2    ][j] = __low2half(h2);
            VTs[dp*2 + 1][j] = __high2half(h2);
        }
        __syncthreads();

        #pragma unroll
        for (int ng = 0; ng < 8; ng++) {
            const int kb = ng*16;
            float s[2][2][4] = {};
            #pragma unroll
            for (int kt = 0; kt < 2; kt++) {
                uint32_t b[2][2];
                #pragma unroll
                for (int j = 0; j < 2; j++) {
                    int key = kb + j*8 + g;
                    b[j][0] = *(const uint32_t*)&Ks[key][kt*16 + 2*tc    ];
                    b[j][1] = *(const uint32_t*)&Ks[key][kt*16 + 2*tc + 8];
                }
                #pragma unroll
                for (int mt = 0; mt < 2; mt++)
                    #pragma unroll
                    for (int j = 0; j < 2; j++)
                        mma16816(s[mt][j], qa[mt][kt], b[j]);
            }
            uint32_t pa[2][4];
            #pragma unroll
            for (int mt = 0; mt < 2; mt++) {
                #pragma unroll
                for (int hi = 0; hi < 2; hi++) {
                    float rm = fmaxf(fmaxf(s[mt][0][2*hi], s[mt][0][2*hi+1]),
                                     fmaxf(s[mt][1][2*hi], s[mt][1][2*hi+1]));
                    rm = fmaxf(rm, __shfl_xor_sync(0xffffffffu, rm, 1));
                    rm = fmaxf(rm, __shfl_xor_sync(0xffffffffu, rm, 2));
                    float mold = mrow[mt*2 + hi];
                    float mnew = fmaxf(mold, rm);
                    float p00 = exp2f(s[mt][0][2*hi]   - mnew);
                    float p01 = exp2f(s[mt][0][2*hi+1] - mnew);
                    float p10 = exp2f(s[mt][1][2*hi]   - mnew);
                    float p11 = exp2f(s[mt][1][2*hi+1] - mnew);
                    float psum = p00 + p01 + p10 + p11;
                    if (rm > mold) {
                        float cf = exp2f(mold - mnew);
                        mrow[mt*2 + hi] = mnew;
                        lacc[mt*2 + hi] = lacc[mt*2 + hi]*cf + psum;
                        #pragma unroll
                        for (int dj = 0; dj < 4; dj++) {
                            oacc[mt][dj][2*hi]   *= cf;
                            oacc[mt][dj][2*hi+1] *= cf;
                        }
                    } else {
                        lacc[mt*2 + hi] += psum;
                    }
                    pa[mt][0*2 + hi] = packh2(p00, p01);
                    pa[mt][1*2 + hi] = packh2(p10, p11);
                }
            }
            #pragma unroll
            for (int dj = 0; dj < 4; dj++) {
                uint32_t vb[2];
                vb[0] = *(const uint32_t*)&VTs[dj*8 + g][kb + 2*tc    ];
                vb[1] = *(const uint32_t*)&VTs[dj*8 + g][kb + 2*tc + 8];
                #pragma unroll
                for (int mt = 0; mt < 2; mt++)
                    mma16816(oacc[mt][dj], pa[mt], vb);
            }
        }
    }

    #pragma unroll
    for (int i = 0; i < 4; i++) {
        lacc[i] += __shfl_xor_sync(0xffffffffu, lacc[i], 1);
        lacc[i] += __shfl_xor_sync(0xffffffffu, lacc[i], 2);
    }
    #pragma unroll
    for (int mt = 0; mt < 2; mt++) {
        int rbase = q0 + w*32 + mt*16;
        float inv0 = 1.f / lacc[mt*2 + 0];
        float inv1 = 1.f / lacc[mt*2 + 1];
        #pragma unroll
        for (int dj = 0; dj < 4; dj++) {
            int col = hoff + dj*8 + 2*tc;
            *(float2*)&Og[(rbase + g    )*CC + col] =
                make_float2(oacc[mt][dj][0]*inv0, oacc[mt][dj][1]*inv0);
            *(float2*)&Og[(rbase + g + 8)*CC + col] =
                make_float2(oacc[mt][dj][2]*inv1, oacc[mt][dj][3]*inv1);
        }
    }
}

// ---------------- small kernels ----------------
__global__ void lin1_kernel(const float* __restrict__ x, const float* __restrict__ w,
                            const float* __restrict__ b) {
    int n = blockIdx.x, c = threadIdx.x;
    g_h[n*CC + c] = x[n]*w[c] + b[c];
}

__global__ void zero_kernel(float* __restrict__ p, int n) {
    int i = blockIdx.x*blockDim.x + threadIdx.x;
    if (i < n) p[i] = 0.f;
}

__global__ void zero_stats_kernel() {
    int i = blockIdx.x*256 + threadIdx.x;
    g_sum[i] = 0.f;
    g_sumsq[i] = 0.f;
}

// vectorized scatter: thread = (edge quarter, 4 channels); LDG.128 + RED.v4
__global__ void scatter_kernel(const int* __restrict__ ei, int E) {
    const int* src = ei;
    const int* dst = ei + E;
    int e = blockIdx.x*4 + (threadIdx.x >> 6);
    int c4 = (threadIdx.x & 63) * 4;
    int s = src[e], d = dst[e];
    float4 val = *(const float4*)&g_h[s*CC + c4];
    float* p = &g_agg[d*CC + c4];
    asm volatile("red.global.add.v4.f32 [%0], {%1, %2, %3, %4};"
                 :: "l"(p), "f"(val.x), "f"(val.y), "f"(val.z), "f"(val.w)
                 : "memory");
}

__global__ void bn_stats_kernel(const float* __restrict__ in1, const float* __restrict__ in2,
                                int statoff) {
    int c = threadIdx.x;
    int r0 = blockIdx.x * 32;
    float s = 0.f, ss = 0.f;
    #pragma unroll 4
    for (int r = r0; r < r0 + 32; r++) {
        float v = in1[r*CC + c] + in2[r*CC + c];
        s += v; ss += v*v;
    }
    atomicAdd(&g_sum[statoff + c], s);
    atomicAdd(&g_sumsq[statoff + c], ss);
}

__global__ void bn_apply_kernel(const float* __restrict__ in1, const float* __restrict__ in2,
                                int statoff,
                                const float* __restrict__ gamma, const float* __restrict__ beta,
                                const float* __restrict__ addend, float* __restrict__ out) {
    int i = blockIdx.x*256 + threadIdx.x;
    int c = i & (CC-1);
    float mean = g_sum[statoff + c] * (1.f/NN);
    float var  = g_sumsq[statoff + c] * (1.f/NN) - mean*mean;
    float v = in1[i] + in2[i];
    float r = (v - mean) * rsqrtf(var + EPSV) * gamma[c] + beta[c];
    if (addend) r += addend[i];
    out[i] = r;
}

// ---------------- host ----------------
extern "C" void kernel_launch(void* const* d_in, const int* in_sizes, int n_in,
                              void* d_out, int out_size) {
    const float* x      = (const float*)d_in[0];
    const int*   ei     = (const int*)  d_in[1];
    const float* lin1_w = (const float*)d_in[2];
    const float* lin1_b = (const float*)d_in[3];
    const float* gin_b1 = (const float*)d_in[5];
    const float* gin_b2 = (const float*)d_in[7];
    const float* bq = (const float*)d_in[12];
    const float* bk = (const float*)d_in[13];
    const float* bv = (const float*)d_in[14];
    const float* bo = (const float*)d_in[15];
    const float* bn1_g = (const float*)d_in[16];
    const float* bn1_b = (const float*)d_in[17];
    const float* bn2_g = (const float*)d_in[18];
    const float* bn2_b = (const float*)d_in[19];
    const float* bn3_g = (const float*)d_in[20];
    const float* bn3_b = (const float*)d_in[21];
    const float* mb1 = (const float*)d_in[23];
    const float* mb2 = (const float*)d_in[25];
    int E = in_sizes[1] / 2;

    float *h, *agg, *t1, *t2, *q, *t3, *o, *h1;
    cudaGetSymbolAddress((void**)&h,   g_h);
    cudaGetSymbolAddress((void**)&agg, g_agg);
    cudaGetSymbolAddress((void**)&t1,  g_t1);
    cudaGetSymbolAddress((void**)&t2,  g_t2);
    cudaGetSymbolAddress((void**)&q,   g_q);
    cudaGetSymbolAddress((void**)&t3,  g_t3);
    cudaGetSymbolAddress((void**)&o,   g_o);
    cudaGetSymbolAddress((void**)&h1,  g_h1);
    __half *wh, *wl, *qh, *kh, *vh;
    cudaGetSymbolAddress((void**)&wh, g_wh);
    cudaGetSymbolAddress((void**)&wl, g_wl);
    cudaGetSymbolAddress((void**)&qh, g_qh);
    cudaGetSymbolAddress((void**)&kh, g_kh);
    cudaGetSymbolAddress((void**)&vh, g_vh);

    convw_all_kernel<<<(TOTW + 255)/256, 256>>>(
        (const float*)d_in[4], (const float*)d_in[6],
        (const float*)d_in[8], (const float*)d_in[9],
        (const float*)d_in[10], (const float*)d_in[11],
        (const float*)d_in[22], (const float*)d_in[24]);
    zero_stats_kernel<<<9, 256>>>();

    dim3 gN256(CC/64,   NN/128);
    dim3 gN512(2*CC/64, NN/128);
    dim3 gqkv (CC/64,   NN/128, 3);
    int ewgrid = NN*CC/256;

    lin1_kernel<<<NN, CC>>>(x, lin1_w, lin1_b);

    for (int l = 0; l < LL; l++) {
        int w1 = l*CC*CC, w2 = l*2*CC*CC;
        int so = l*3*CC;
        // ---- GIN branch ----
        zero_kernel<<<ewgrid, 256>>>(agg, NN*CC);
        scatter_kernel<<<E/4, 256>>>(ei, E);
        gemm_mma_kernel<<<gN256, 128>>>(h, agg, wh + OFF_GW1 + w1, wl + OFF_GW1 + w1,
                                        gin_b1 + l*CC, t1, CC, CC, 1);
        gemm_mma_kernel<<<gN256, 128>>>(t1, nullptr, wh + OFF_GW2 + w1, wl + OFF_GW2 + w1,
                                        gin_b2 + l*CC, t2, CC, CC, 0);
        bn_stats_kernel<<<128, CC>>>(t2, h, so);
        bn_apply_kernel<<<ewgrid, 256>>>(t2, h, so, bn1_g + l*CC, bn1_b + l*CC, nullptr, h1);
        // ---- global attention ----
        qkv_mma_kernel<<<gqkv, 128>>>(h, wh, wl, bq + l*CC, bk + l*CC, bv + l*CC, l);
        flash_mma_kernel<<<dim3(NN/256, HH), 256>>>(qh, kh, vh, o);
        gemm_mma_kernel<<<gN256, 128>>>(o, nullptr, wh + OFF_WO + w1, wl + OFF_WO + w1,
                                        bo + l*CC, t3, CC, CC, 0);
        bn_stats_kernel<<<128, CC>>>(t3, h, so + CC);
        bn_apply_kernel<<<ewgrid, 256>>>(t3, h, so + CC, bn2_g + l*CC, bn2_b + l*CC, h1, q);
        // ---- feedforward ----
        gemm_mma_kernel<<<gN512, 128>>>(q, nullptr, wh + OFF_MW1 + w2, wl + OFF_MW1 + w2,
                                        mb1 + l*2*CC, t1, 2*CC, CC, 1);
        gemm_mma_kernel<<<gN256, 128>>>(t1, nullptr, wh + OFF_MW2 + w2, wl + OFF_MW2 + w2,
                                        mb2 + l*CC, t2, CC, 2*CC, 0);
        bn_stats_kernel<<<128, CC>>>(t2, q, so + 2*CC);
        bn_apply_kernel<<<ewgrid, 256>>>(t2, q, so + 2*CC, bn3_g + l*CC, bn3_b + l*CC, nullptr,
                                         (l == LL-1) ? (float*)d_out : h);
    }
    (void)n_in; (void)out_size;
}

// round 14
// speedup vs baseline: 1.0983x; 1.0026x over previous
#include <cuda_runtime.h>
#include <cuda_fp16.h>
#include <math.h>
#include <stdint.h>

#define NN 4096
#define CC 256
#define HH 8
#define DHH 32
#define LL 3
#define EPSV 1e-5f
#define QSC (0.17677669529663687f * 1.4426950408889634f)

// ---------------- scratch (no allocation allowed) ----------------
__device__ float g_h[NN*CC];
__device__ float g_agg[NN*CC];
__device__ float g_t1[NN*2*CC];
__device__ float g_t2[NN*CC];
__device__ float g_q[NN*CC];
__device__ float g_t3[NN*CC];
__device__ float g_o[NN*CC];
__device__ float g_h1[NN*CC];
__device__ __half g_qh[NN*CC];
__device__ __half g_kh[NN*CC];
__device__ __half g_vh[NN*CC];
__device__ float g_sum[9*CC];
__device__ float g_sumsq[9*CC];
__device__ int   g_cnt[9];

// fp16 hi/lo weight cache
#define OFF_GW1 0
#define OFF_GW2 196608
#define OFF_WQ  393216
#define OFF_WK  589824
#define OFF_WV  786432
#define OFF_WO  983040
#define OFF_MW1 1179648
#define OFF_MW2 1572864
#define TOTW    1966080
__device__ __half g_wh[TOTW];
__device__ __half g_wl[TOTW];

// ---------------- mma helpers ----------------
__device__ __forceinline__ void mma16816(float* d, const uint32_t* a, const uint32_t* b) {
    asm volatile(
        "mma.sync.aligned.m16n8k16.row.col.f32.f16.f16.f32 "
        "{%0,%1,%2,%3}, {%4,%5,%6,%7}, {%8,%9}, {%0,%1,%2,%3};"
        : "+f"(d[0]), "+f"(d[1]), "+f"(d[2]), "+f"(d[3])
        : "r"(a[0]), "r"(a[1]), "r"(a[2]), "r"(a[3]), "r"(b[0]), "r"(b[1]));
}
__device__ __forceinline__ uint32_t packh2(float x, float y) {
    __half2 h = __floats2half2_rn(x, y);
    return *(uint32_t*)&h;
}

// ---------------- weight conversion ----------------
__global__ void convw_all_kernel(
    const float* __restrict__ gw1, const float* __restrict__ gw2,
    const float* __restrict__ wq,  const float* __restrict__ wk,
    const float* __restrict__ wv,  const float* __restrict__ wo,
    const float* __restrict__ mw1, const float* __restrict__ mw2)
{
    int i = blockIdx.x*256 + threadIdx.x;
    if (i >= TOTW) return;
    const float* src; int off;
    if      (i < OFF_GW2) { src = gw1; off = OFF_GW1; }
    else if (i < OFF_WQ)  { src = gw2; off = OFF_GW2; }
    else if (i < OFF_WK)  { src = wq;  off = OFF_WQ;  }
    else if (i < OFF_WV)  { src = wk;  off = OFF_WK;  }
    else if (i < OFF_WO)  { src = wv;  off = OFF_WV;  }
    else if (i < OFF_MW1) { src = wo;  off = OFF_WO;  }
    else if (i < OFF_MW2) { src = mw1; off = OFF_MW1; }
    else                  { src = mw2; off = OFF_MW2; }
    float x = src[i - off];
    __half h = __float2half_rn(x);
    g_wh[i] = h;
    g_wl[i] = __float2half_rn(x - __half2float(h));
}

// ---------------- HMMA GEMM (3-term hi/lo split); OUTHALF selects fp16 output ----------------
#define APAD 40
template<bool OUTHALF>
__device__ __forceinline__ void gemm_mma_body(
    const float* __restrict__ A1, const float* __restrict__ A2,
    const __half* __restrict__ Bh, const __half* __restrict__ Bl,
    const float* __restrict__ bias, void* __restrict__ Cv,
    int Nout, int K, int relu, int m0, int n0)
{
    __shared__ __half Ah[128][APAD];
    __shared__ __half Al[128][APAD];
    __shared__ __half Bhs[64][APAD];
    __shared__ __half Bls[64][APAD];

    const int tid = threadIdx.x;
    const int w = tid >> 5, lane = tid & 31;
    const int g = lane >> 2, tc = lane & 3;
    const int wm = w & 1, wn = w >> 1;

    float acc[4][4][4] = {};

    for (int k0 = 0; k0 < K; k0 += 32) {
        #pragma unroll
        for (int it = 0; it < 16; it++) {
            int idx = it*128 + tid;
            int r = idx >> 4, c2 = idx & 15;
            const float* p = &A1[(m0 + r)*K + k0 + c2*2];
            float ax = p[0], ay = p[1];
            if (A2) { const float* p2 = &A2[(m0 + r)*K + k0 + c2*2]; ax += p2[0]; ay += p2[1]; }
            __half hx = __float2half_rn(ax), hy = __float2half_rn(ay);
            Ah[r][c2*2]   = hx; Ah[r][c2*2+1] = hy;
            Al[r][c2*2]   = __float2half_rn(ax - __half2float(hx));
            Al[r][c2*2+1] = __float2half_rn(ay - __half2float(hy));
        }
        #pragma unroll
        for (int it = 0; it < 8; it++) {
            int idx = it*128 + tid;
            int r = idx >> 4, c2 = idx & 15;
            *(__half2*)&Bhs[r][c2*2] = *(const __half2*)&Bh[(n0 + r)*K + k0 + c2*2];
            *(__half2*)&Bls[r][c2*2] = *(const __half2*)&Bl[(n0 + r)*K + k0 + c2*2];
        }
        __syncthreads();

        #pragma unroll
        for (int kt = 0; kt < 2; kt++) {
            uint32_t ah[4][4], al[4][4], bh[4][2], bl[4][2];
            #pragma unroll
            for (int mt = 0; mt < 4; mt++) {
                int rb = wm*64 + mt*16 + g;
                int c = kt*16 + 2*tc;
                ah[mt][0] = *(const uint32_t*)&Ah[rb    ][c];
                ah[mt][1] = *(const uint32_t*)&Ah[rb + 8][c];
                ah[mt][2] = *(const uint32_t*)&Ah[rb    ][c + 8];
                ah[mt][3] = *(const uint32_t*)&Ah[rb + 8][c + 8];
                al[mt][0] = *(const uint32_t*)&Al[rb    ][c];
                al[mt][1] = *(const uint32_t*)&Al[rb + 8][c];
                al[mt][2] = *(const uint32_t*)&Al[rb    ][c + 8];
                al[mt][3] = *(const uint32_t*)&Al[rb + 8][c + 8];
            }
            #pragma unroll
            for (int nt = 0; nt < 4; nt++) {
                int nb = wn*32 + nt*8 + g;
                int c = kt*16 + 2*tc;
                bh[nt][0] = *(const uint32_t*)&Bhs[nb][c];
                bh[nt][1] = *(const uint32_t*)&Bhs[nb][c + 8];
                bl[nt][0] = *(const uint32_t*)&Bls[nb][c];
                bl[nt][1] = *(const uint32_t*)&Bls[nb][c + 8];
            }
            #pragma unroll
            for (int mt = 0; mt < 4; mt++)
                #pragma unroll
                for (int nt = 0; nt < 4; nt++) {
                    mma16816(acc[mt][nt], ah[mt], bh[nt]);
                    mma16816(acc[mt][nt], al[mt], bh[nt]);
                    mma16816(acc[mt][nt], ah[mt], bl[nt]);
                }
        }
        __syncthreads();
    }

    #pragma unroll
    for (int mt = 0; mt < 4; mt++) {
        int row = m0 + wm*64 + mt*16 + g;
        #pragma unroll
        for (int nt = 0; nt < 4; nt++) {
            int col = n0 + wn*32 + nt*8 + 2*tc;
            float b0 = bias[col], b1 = bias[col + 1];
            float v0 = acc[mt][nt][0] + b0, v1 = acc[mt][nt][1] + b1;
            float v2 = acc[mt][nt][2] + b0, v3 = acc[mt][nt][3] + b1;
            if (relu) {
                v0 = fmaxf(v0, 0.f); v1 = fmaxf(v1, 0.f);
                v2 = fmaxf(v2, 0.f); v3 = fmaxf(v3, 0.f);
            }
            if (OUTHALF) {
                __half* C = (__half*)Cv;
                *(__half2*)&C[row*Nout + col]       = __floats2half2_rn(v0, v1);
                *(__half2*)&C[(row + 8)*Nout + col] = __floats2half2_rn(v2, v3);
            } else {
                float* C = (float*)Cv;
                *(float2*)&C[row*Nout + col]       = make_float2(v0, v1);
                *(float2*)&C[(row + 8)*Nout + col] = make_float2(v2, v3);
            }
        }
    }
}

__global__ void __launch_bounds__(128) gemm_mma_kernel(
    const float* __restrict__ A1, const float* __restrict__ A2,
    const __half* __restrict__ Bh, const __half* __restrict__ Bl,
    const float* __restrict__ bias, float* __restrict__ C,
    int Nout, int K, int relu)
{
    gemm_mma_body<false>(A1, A2, Bh, Bl, bias, C, Nout, K, relu,
                         blockIdx.y*128, blockIdx.x*64);
}

__global__ void __launch_bounds__(128) qkv_mma_kernel(
    const float* __restrict__ A, const __half* __restrict__ wh,
    const __half* __restrict__ wl,
    const float* __restrict__ bq, const float* __restrict__ bk,
    const float* __restrict__ bv, int l)
{
    const __half *Bh, *Bl; const float* bias; __half* C;
    int woff = l*CC*CC;
    if (blockIdx.z == 0)      { Bh = wh + OFF_WQ + woff; Bl = wl + OFF_WQ + woff; bias = bq; C = g_qh; }
    else if (blockIdx.z == 1) { Bh = wh + OFF_WK + woff; Bl = wl + OFF_WK + woff; bias = bk; C = g_kh; }
    else                      { Bh = wh + OFF_WV + woff; Bl = wl + OFF_WV + woff; bias = bv; C = g_vh; }
    gemm_mma_body<true>(A, nullptr, Bh, Bl, bias, C, CC, CC, 0,
                        blockIdx.y*128, blockIdx.x*64);
}

// ---------------- flash attention (fp16 in gmem, fp16 mma, online softmax) ----------------
#define QPAD 36
#define VPAD 132
__global__ void __launch_bounds__(256) flash_mma_kernel(
    const __half* __restrict__ Q, const __half* __restrict__ Kp,
    const __half* __restrict__ V, float* __restrict__ Og)
{
    __shared__ __half Qs[256][QPAD];
    __shared__ __half Ks[128][QPAD];
    __shared__ __half VTs[32][VPAD];

    const int tid = threadIdx.x;
    const int w = tid >> 5, lane = tid & 31;
    const int g = lane >> 2, tc = lane & 3;
    const int hoff = blockIdx.y * DHH;
    const int q0 = blockIdx.x * 256;
    const __half2 qsc2 = __float2half2_rn(QSC);

    #pragma unroll
    for (int it = 0; it < 16; it++) {
        int idx = it*256 + tid;
        int r = idx >> 4, pr = idx & 15;
        __half2 h2 = *(const __half2*)&Q[(q0 + r)*CC + hoff + pr*2];
        *(__half2*)&Qs[r][pr*2] = __hmul2(h2, qsc2);
    }
    __syncthreads();

    uint32_t qa[2][2][4];
    #pragma unroll
    for (int mt = 0; mt < 2; mt++) {
        #pragma unroll
        for (int kt = 0; kt < 2; kt++) {
            int r0 = w*32 + mt*16 + g;
            qa[mt][kt][0] = *(const uint32_t*)&Qs[r0    ][kt*16 + 2*tc    ];
            qa[mt][kt][1] = *(const uint32_t*)&Qs[r0 + 8][kt*16 + 2*tc    ];
            qa[mt][kt][2] = *(const uint32_t*)&Qs[r0    ][kt*16 + 2*tc + 8];
            qa[mt][kt][3] = *(const uint32_t*)&Qs[r0 + 8][kt*16 + 2*tc + 8];
        }
    }

    float oacc[2][4][4] = {};
    float lacc[4] = {};
    float mrow[4] = {-1e30f, -1e30f, -1e30f, -1e30f};

    for (int j0 = 0; j0 < NN; j0 += 128) {
        __syncthreads();
        #pragma unroll
        for (int it = 0; it < 8; it++) {
            int idx = it*256 + tid;
            int r = idx >> 4, pr = idx & 15;
            *(uint32_t*)&Ks[r][pr*2] = *(const uint32_t*)&Kp[(j0 + r)*CC + hoff + pr*2];
        }
        #pragma unroll
        for (int it = 0; it < 8; it++) {
            int idx = it*256 + tid;
            int j = idx >> 4, dp = idx & 15;
            __half2 h2 = *(const __half2*)&V[(j0 + j)*CC + hoff + dp*2];
            VTs[dp*2    ][j] = __low2half(h2);
            VTs[dp*2 + 1][j] = __high2half(h2);
        }
        __syncthreads();

        #pragma unroll
        for (int ng = 0; ng < 8; ng++) {
            const int kb = ng*16;
            float s[2][2][4] = {};
            #pragma unroll
            for (int kt = 0; kt < 2; kt++) {
                uint32_t b[2][2];
                #pragma unroll
                for (int j = 0; j < 2; j++) {
                    int key = kb + j*8 + g;
                    b[j][0] = *(const uint32_t*)&Ks[key][kt*16 + 2*tc    ];
                    b[j][1] = *(const uint32_t*)&Ks[key][kt*16 + 2*tc + 8];
                }
                #pragma unroll
                for (int mt = 0; mt < 2; mt++)
                    #pragma unroll
                    for (int j = 0; j < 2; j++)
                        mma16816(s[mt][j], qa[mt][kt], b[j]);
            }
            uint32_t pa[2][4];
            #pragma unroll
            for (int mt = 0; mt < 2; mt++) {
                #pragma unroll
                for (int hi = 0; hi < 2; hi++) {
                    float rm = fmaxf(fmaxf(s[mt][0][2*hi], s[mt][0][2*hi+1]),
                                     fmaxf(s[mt][1][2*hi], s[mt][1][2*hi+1]));
                    rm = fmaxf(rm, __shfl_xor_sync(0xffffffffu, rm, 1));
                    rm = fmaxf(rm, __shfl_xor_sync(0xffffffffu, rm, 2));
                    float mold = mrow[mt*2 + hi];
                    float mnew = fmaxf(mold, rm);
                    float p00 = exp2f(s[mt][0][2*hi]   - mnew);
                    float p01 = exp2f(s[mt][0][2*hi+1] - mnew);
                    float p10 = exp2f(s[mt][1][2*hi]   - mnew);
                    float p11 = exp2f(s[mt][1][2*hi+1] - mnew);
                    float psum = p00 + p01 + p10 + p11;
                    if (rm > mold) {
                        float cf = exp2f(mold - mnew);
                        mrow[mt*2 + hi] = mnew;
                        lacc[mt*2 + hi] = lacc[mt*2 + hi]*cf + psum;
                        #pragma unroll
                        for (int dj = 0; dj < 4; dj++) {
                            oacc[mt][dj][2*hi]   *= cf;
                            oacc[mt][dj][2*hi+1] *= cf;
                        }
                    } else {
                        lacc[mt*2 + hi] += psum;
                    }
                    pa[mt][0*2 + hi] = packh2(p00, p01);
                    pa[mt][1*2 + hi] = packh2(p10, p11);
                }
            }
            #pragma unroll
            for (int dj = 0; dj < 4; dj++) {
                uint32_t vb[2];
                vb[0] = *(const uint32_t*)&VTs[dj*8 + g][kb + 2*tc    ];
                vb[1] = *(const uint32_t*)&VTs[dj*8 + g][kb + 2*tc + 8];
                #pragma unroll
                for (int mt = 0; mt < 2; mt++)
                    mma16816(oacc[mt][dj], pa[mt], vb);
            }
        }
    }

    #pragma unroll
    for (int i = 0; i < 4; i++) {
        lacc[i] += __shfl_xor_sync(0xffffffffu, lacc[i], 1);
        lacc[i] += __shfl_xor_sync(0xffffffffu, lacc[i], 2);
    }
    #pragma unroll
    for (int mt = 0; mt < 2; mt++) {
        int rbase = q0 + w*32 + mt*16;
        float inv0 = 1.f / lacc[mt*2 + 0];
        float inv1 = 1.f / lacc[mt*2 + 1];
        #pragma unroll
        for (int dj = 0; dj < 4; dj++) {
            int col = hoff + dj*8 + 2*tc;
            *(float2*)&Og[(rbase + g    )*CC + col] =
                make_float2(oacc[mt][dj][0]*inv0, oacc[mt][dj][1]*inv0);
            *(float2*)&Og[(rbase + g + 8)*CC + col] =
                make_float2(oacc[mt][dj][2]*inv1, oacc[mt][dj][3]*inv1);
        }
    }
}

// ---------------- small kernels ----------------
__global__ void lin1_kernel(const float* __restrict__ x, const float* __restrict__ w,
                            const float* __restrict__ b) {
    int n = blockIdx.x, c = threadIdx.x;
    g_h[n*CC + c] = x[n]*w[c] + b[c];
}

__global__ void zero_kernel(float* __restrict__ p, int n) {
    int i = blockIdx.x*blockDim.x + threadIdx.x;
    if (i < n) p[i] = 0.f;
}

__global__ void zero_stats_kernel() {
    int i = blockIdx.x*256 + threadIdx.x;
    g_sum[i] = 0.f;
    g_sumsq[i] = 0.f;
    if (blockIdx.x == 0 && threadIdx.x < 9) g_cnt[threadIdx.x] = 0;
}

__global__ void scatter_kernel(const int* __restrict__ ei, int E) {
    const int* src = ei;
    const int* dst = ei + E;
    int e = blockIdx.x*4 + (threadIdx.x >> 6);
    int c4 = (threadIdx.x & 63) * 4;
    int s = src[e], d = dst[e];
    float4 val = *(const float4*)&g_h[s*CC + c4];
    float* p = &g_agg[d*CC + c4];
    asm volatile("red.global.add.v4.f32 [%0], {%1, %2, %3, %4};"
                 :: "l"(p), "f"(val.x), "f"(val.y), "f"(val.z), "f"(val.w)
                 : "memory");
}

// ---------------- fused BN: stats + grid-sync + apply, one launch ----------------
// grid 128 CTAs x 256 threads (all co-resident on 148 SMs -> spin barrier safe).
// v = in1 + in2 held in registers across the barrier; out = BN(v)*g + b (+ addend).
__global__ void __launch_bounds__(256) bn_fused_kernel(
    const float* __restrict__ in1, const float* __restrict__ in2,
    int slot,
    const float* __restrict__ gamma, const float* __restrict__ beta,
    const float* __restrict__ addend, float* __restrict__ out)
{
    const int c = threadIdx.x;
    const int r0 = blockIdx.x * 32;
    const int statoff = slot * CC;

    float v[32];
    float s = 0.f, ss = 0.f;
    #pragma unroll 4
    for (int i = 0; i < 32; i++) {
        float x = in1[(r0 + i)*CC + c] + in2[(r0 + i)*CC + c];
        v[i] = x;
        s += x; ss += x*x;
    }
    atomicAdd(&g_sum[statoff + c], s);
    atomicAdd(&g_sumsq[statoff + c], ss);
    __threadfence();
    __syncthreads();
    if (threadIdx.x == 0) atomicAdd(&g_cnt[slot], 1);
    if (threadIdx.x == 0) {
        while (atomicAdd(&g_cnt[slot], 0) < (int)gridDim.x) { }
    }
    __syncthreads();

    float mean = g_sum[statoff + c] * (1.f/NN);
    float var  = g_sumsq[statoff + c] * (1.f/NN) - mean*mean;
    float scale = rsqrtf(var + EPSV) * gamma[c];
    float shift = beta[c] - mean * scale;
    #pragma unroll 4
    for (int i = 0; i < 32; i++) {
        float r = v[i] * scale + shift;
        if (addend) r += addend[(r0 + i)*CC + c];
        out[(r0 + i)*CC + c] = r;
    }
}

// ---------------- host ----------------
extern "C" void kernel_launch(void* const* d_in, const int* in_sizes, int n_in,
                              void* d_out, int out_size) {
    const float* x      = (const float*)d_in[0];
    const int*   ei     = (const int*)  d_in[1];
    const float* lin1_w = (const float*)d_in[2];
    const float* lin1_b = (const float*)d_in[3];
    const float* gin_b1 = (const float*)d_in[5];
    const float* gin_b2 = (const float*)d_in[7];
    const float* bq = (const float*)d_in[12];
    const float* bk = (const float*)d_in[13];
    const float* bv = (const float*)d_in[14];
    const float* bo = (const float*)d_in[15];
    const float* bn1_g = (const float*)d_in[16];
    const float* bn1_b = (const float*)d_in[17];
    const float* bn2_g = (const float*)d_in[18];
    const float* bn2_b = (const float*)d_in[19];
    const float* bn3_g = (const float*)d_in[20];
    const float* bn3_b = (const float*)d_in[21];
    const float* mb1 = (const float*)d_in[23];
    const float* mb2 = (const float*)d_in[25];
    int E = in_sizes[1] / 2;

    float *h, *agg, *t1, *t2, *q, *t3, *o, *h1;
    cudaGetSymbolAddress((void**)&h,   g_h);
    cudaGetSymbolAddress((void**)&agg, g_agg);
    cudaGetSymbolAddress((void**)&t1,  g_t1);
    cudaGetSymbolAddress((void**)&t2,  g_t2);
    cudaGetSymbolAddress((void**)&q,   g_q);
    cudaGetSymbolAddress((void**)&t3,  g_t3);
    cudaGetSymbolAddress((void**)&o,   g_o);
    cudaGetSymbolAddress((void**)&h1,  g_h1);
    __half *wh, *wl, *qh, *kh, *vh;
    cudaGetSymbolAddress((void**)&wh, g_wh);
    cudaGetSymbolAddress((void**)&wl, g_wl);
    cudaGetSymbolAddress((void**)&qh, g_qh);
    cudaGetSymbolAddress((void**)&kh, g_kh);
    cudaGetSymbolAddress((void**)&vh, g_vh);

    convw_all_kernel<<<(TOTW + 255)/256, 256>>>(
        (const float*)d_in[4], (const float*)d_in[6],
        (const float*)d_in[8], (const float*)d_in[9],
        (const float*)d_in[10], (const float*)d_in[11],
        (const float*)d_in[22], (const float*)d_in[24]);
    zero_stats_kernel<<<9, 256>>>();

    dim3 gN256(CC/64,   NN/128);
    dim3 gN512(2*CC/64, NN/128);
    dim3 gqkv (CC/64,   NN/128, 3);
    int ewgrid = NN*CC/256;

    lin1_kernel<<<NN, CC>>>(x, lin1_w, lin1_b);

    for (int l = 0; l < LL; l++) {
        int w1 = l*CC*CC, w2 = l*2*CC*CC;
        int sl = l*3;
        // ---- GIN branch ----
        zero_kernel<<<ewgrid, 256>>>(agg, NN*CC);
        scatter_kernel<<<E/4, 256>>>(ei, E);
        gemm_mma_kernel<<<gN256, 128>>>(h, agg, wh + OFF_GW1 + w1, wl + OFF_GW1 + w1,
                                        gin_b1 + l*CC, t1, CC, CC, 1);
        gemm_mma_kernel<<<gN256, 128>>>(t1, nullptr, wh + OFF_GW2 + w1, wl + OFF_GW2 + w1,
                                        gin_b2 + l*CC, t2, CC, CC, 0);
        bn_fused_kernel<<<128, 256>>>(t2, h, sl, bn1_g + l*CC, bn1_b + l*CC, nullptr, h1);
        // ---- global attention ----
        qkv_mma_kernel<<<gqkv, 128>>>(h, wh, wl, bq + l*CC, bk + l*CC, bv + l*CC, l);
        flash_mma_kernel<<<dim3(NN/256, HH), 256>>>(qh, kh, vh, o);
        gemm_mma_kernel<<<gN256, 128>>>(o, nullptr, wh + OFF_WO + w1, wl + OFF_WO + w1,
                                        bo + l*CC, t3, CC, CC, 0);
        bn_fused_kernel<<<128, 256>>>(t3, h, sl + 1, bn2_g + l*CC, bn2_b + l*CC, h1, q);
        // ---- feedforward ----
        gemm_mma_kernel<<<gN512, 128>>>(q, nullptr, wh + OFF_MW1 + w2, wl + OFF_MW1 + w2,
                                        mb1 + l*2*CC, t1, 2*CC, CC, 1);
        gemm_mma_kernel<<<gN256, 128>>>(t1, nullptr, wh + OFF_MW2 + w2, wl + OFF_MW2 + w2,
                                        mb2 + l*CC, t2, CC, 2*CC, 0);
        bn_fused_kernel<<<128, 256>>>(t2, q, sl + 2, bn3_g + l*CC, bn3_b + l*CC, nullptr,
                                      (l == LL-1) ? (float*)d_out : h);
    }
    (void)n_in; (void)out_size;
}

// round 15
// speedup vs baseline: 1.1291x; 1.0280x over previous
#include <cuda_runtime.h>
#include <cuda_fp16.h>
#include <math.h>
#include <stdint.h>

#define NN 4096
#define CC 256
#define HH 8
#define DHH 32
#define LL 3
#define EPSV 1e-5f
#define QSC (0.17677669529663687f * 1.4426950408889634f)

// ---------------- scratch (no allocation allowed) ----------------
__device__ float g_h[NN*CC];
__device__ float g_agg[NN*CC];
__device__ float g_t1[NN*2*CC];
__device__ float g_t2[NN*CC];
__device__ float g_q[NN*CC];
__device__ float g_t3[NN*CC];
__device__ float g_o[NN*CC];
__device__ float g_h1[NN*CC];
__device__ __half g_qh[NN*CC];
__device__ __half g_kh[NN*CC];
__device__ __half g_vh[NN*CC];
__device__ float g_sum[9*CC];
__device__ float g_sumsq[9*CC];
__device__ int   g_cnt[9];

// fp16 hi/lo weight cache
#define OFF_GW1 0
#define OFF_GW2 196608
#define OFF_WQ  393216
#define OFF_WK  589824
#define OFF_WV  786432
#define OFF_WO  983040
#define OFF_MW1 1179648
#define OFF_MW2 1572864
#define TOTW    1966080
__device__ __half g_wh[TOTW];
__device__ __half g_wl[TOTW];

// ---------------- helpers ----------------
__device__ __forceinline__ void mma16816(float* d, const uint32_t* a, const uint32_t* b) {
    asm volatile(
        "mma.sync.aligned.m16n8k16.row.col.f32.f16.f16.f32 "
        "{%0,%1,%2,%3}, {%4,%5,%6,%7}, {%8,%9}, {%0,%1,%2,%3};"
        : "+f"(d[0]), "+f"(d[1]), "+f"(d[2]), "+f"(d[3])
        : "r"(a[0]), "r"(a[1]), "r"(a[2]), "r"(a[3]), "r"(b[0]), "r"(b[1]));
}
__device__ __forceinline__ uint32_t packh2(float x, float y) {
    __half2 h = __floats2half2_rn(x, y);
    return *(uint32_t*)&h;
}
// guaranteed single MUFU.EX2 (exp2f is a software routine without --use_fast_math)
__device__ __forceinline__ float ex2(float x) {
    float r;
    asm("ex2.approx.ftz.f32 %0, %1;" : "=f"(r) : "f"(x));
    return r;
}

// ---------------- weight conversion ----------------
__global__ void convw_all_kernel(
    const float* __restrict__ gw1, const float* __restrict__ gw2,
    const float* __restrict__ wq,  const float* __restrict__ wk,
    const float* __restrict__ wv,  const float* __restrict__ wo,
    const float* __restrict__ mw1, const float* __restrict__ mw2)
{
    int i = blockIdx.x*256 + threadIdx.x;
    if (i >= TOTW) return;
    const float* src; int off;
    if      (i < OFF_GW2) { src = gw1; off = OFF_GW1; }
    else if (i < OFF_WQ)  { src = gw2; off = OFF_GW2; }
    else if (i < OFF_WK)  { src = wq;  off = OFF_WQ;  }
    else if (i < OFF_WV)  { src = wk;  off = OFF_WK;  }
    else if (i < OFF_WO)  { src = wv;  off = OFF_WV;  }
    else if (i < OFF_MW1) { src = wo;  off = OFF_WO;  }
    else if (i < OFF_MW2) { src = mw1; off = OFF_MW1; }
    else                  { src = mw2; off = OFF_MW2; }
    float x = src[i - off];
    __half h = __float2half_rn(x);
    g_wh[i] = h;
    g_wl[i] = __float2half_rn(x - __half2float(h));
}

// ---------------- HMMA GEMM (3-term hi/lo split); OUTHALF selects fp16 output ----------------
#define APAD 40
template<bool OUTHALF>
__device__ __forceinline__ void gemm_mma_body(
    const float* __restrict__ A1, const float* __restrict__ A2,
    const __half* __restrict__ Bh, const __half* __restrict__ Bl,
    const float* __restrict__ bias, void* __restrict__ Cv,
    int Nout, int K, int relu, int m0, int n0)
{
    __shared__ __half Ah[128][APAD];
    __shared__ __half Al[128][APAD];
    __shared__ __half Bhs[64][APAD];
    __shared__ __half Bls[64][APAD];

    const int tid = threadIdx.x;
    const int w = tid >> 5, lane = tid & 31;
    const int g = lane >> 2, tc = lane & 3;
    const int wm = w & 1, wn = w >> 1;

    float acc[4][4][4] = {};

    for (int k0 = 0; k0 < K; k0 += 32) {
        #pragma unroll
        for (int it = 0; it < 16; it++) {
            int idx = it*128 + tid;
            int r = idx >> 4, c2 = idx & 15;
            const float* p = &A1[(m0 + r)*K + k0 + c2*2];
            float ax = p[0], ay = p[1];
            if (A2) { const float* p2 = &A2[(m0 + r)*K + k0 + c2*2]; ax += p2[0]; ay += p2[1]; }
            __half hx = __float2half_rn(ax), hy = __float2half_rn(ay);
            Ah[r][c2*2]   = hx; Ah[r][c2*2+1] = hy;
            Al[r][c2*2]   = __float2half_rn(ax - __half2float(hx));
            Al[r][c2*2+1] = __float2half_rn(ay - __half2float(hy));
        }
        #pragma unroll
        for (int it = 0; it < 8; it++) {
            int idx = it*128 + tid;
            int r = idx >> 4, c2 = idx & 15;
            *(__half2*)&Bhs[r][c2*2] = *(const __half2*)&Bh[(n0 + r)*K + k0 + c2*2];
            *(__half2*)&Bls[r][c2*2] = *(const __half2*)&Bl[(n0 + r)*K + k0 + c2*2];
        }
        __syncthreads();

        #pragma unroll
        for (int kt = 0; kt < 2; kt++) {
            uint32_t ah[4][4], al[4][4], bh[4][2], bl[4][2];
            #pragma unroll
            for (int mt = 0; mt < 4; mt++) {
                int rb = wm*64 + mt*16 + g;
                int c = kt*16 + 2*tc;
                ah[mt][0] = *(const uint32_t*)&Ah[rb    ][c];
                ah[mt][1] = *(const uint32_t*)&Ah[rb + 8][c];
                ah[mt][2] = *(const uint32_t*)&Ah[rb    ][c + 8];
                ah[mt][3] = *(const uint32_t*)&Ah[rb + 8][c + 8];
                al[mt][0] = *(const uint32_t*)&Al[rb    ][c];
                al[mt][1] = *(const uint32_t*)&Al[rb + 8][c];
                al[mt][2] = *(const uint32_t*)&Al[rb    ][c + 8];
                al[mt][3] = *(const uint32_t*)&Al[rb + 8][c + 8];
            }
            #pragma unroll
            for (int nt = 0; nt < 4; nt++) {
                int nb = wn*32 + nt*8 + g;
                int c = kt*16 + 2*tc;
                bh[nt][0] = *(const uint32_t*)&Bhs[nb][c];
                bh[nt][1] = *(const uint32_t*)&Bhs[nb][c + 8];
                bl[nt][0] = *(const uint32_t*)&Bls[nb][c];
                bl[nt][1] = *(const uint32_t*)&Bls[nb][c + 8];
            }
            #pragma unroll
            for (int mt = 0; mt < 4; mt++)
                #pragma unroll
                for (int nt = 0; nt < 4; nt++) {
                    mma16816(acc[mt][nt], ah[mt], bh[nt]);
                    mma16816(acc[mt][nt], al[mt], bh[nt]);
                    mma16816(acc[mt][nt], ah[mt], bl[nt]);
                }
        }
        __syncthreads();
    }

    #pragma unroll
    for (int mt = 0; mt < 4; mt++) {
        int row = m0 + wm*64 + mt*16 + g;
        #pragma unroll
        for (int nt = 0; nt < 4; nt++) {
            int col = n0 + wn*32 + nt*8 + 2*tc;
            float b0 = bias[col], b1 = bias[col + 1];
            float v0 = acc[mt][nt][0] + b0, v1 = acc[mt][nt][1] + b1;
            float v2 = acc[mt][nt][2] + b0, v3 = acc[mt][nt][3] + b1;
            if (relu) {
                v0 = fmaxf(v0, 0.f); v1 = fmaxf(v1, 0.f);
                v2 = fmaxf(v2, 0.f); v3 = fmaxf(v3, 0.f);
            }
            if (OUTHALF) {
                __half* C = (__half*)Cv;
                *(__half2*)&C[row*Nout + col]       = __floats2half2_rn(v0, v1);
                *(__half2*)&C[(row + 8)*Nout + col] = __floats2half2_rn(v2, v3);
            } else {
                float* C = (float*)Cv;
                *(float2*)&C[row*Nout + col]       = make_float2(v0, v1);
                *(float2*)&C[(row + 8)*Nout + col] = make_float2(v2, v3);
            }
        }
    }
}

__global__ void __launch_bounds__(128) gemm_mma_kernel(
    const float* __restrict__ A1, const float* __restrict__ A2,
    const __half* __restrict__ Bh, const __half* __restrict__ Bl,
    const float* __restrict__ bias, float* __restrict__ C,
    int Nout, int K, int relu)
{
    gemm_mma_body<false>(A1, A2, Bh, Bl, bias, C, Nout, K, relu,
                         blockIdx.y*128, blockIdx.x*64);
}

__global__ void __launch_bounds__(128) qkv_mma_kernel(
    const float* __restrict__ A, const __half* __restrict__ wh,
    const __half* __restrict__ wl,
    const float* __restrict__ bq, const float* __restrict__ bk,
    const float* __restrict__ bv, int l)
{
    const __half *Bh, *Bl; const float* bias; __half* C;
    int woff = l*CC*CC;
    if (blockIdx.z == 0)      { Bh = wh + OFF_WQ + woff; Bl = wl + OFF_WQ + woff; bias = bq; C = g_qh; }
    else if (blockIdx.z == 1) { Bh = wh + OFF_WK + woff; Bl = wl + OFF_WK + woff; bias = bk; C = g_kh; }
    else                      { Bh = wh + OFF_WV + woff; Bl = wl + OFF_WV + woff; bias = bv; C = g_vh; }
    gemm_mma_body<true>(A, nullptr, Bh, Bl, bias, C, CC, CC, 0,
                        blockIdx.y*128, blockIdx.x*64);
}

// ---------------- flash attention (fp16 in gmem, fp16 mma, online softmax) ----------------
#define QPAD 36
#define VPAD 132
__global__ void __launch_bounds__(256) flash_mma_kernel(
    const __half* __restrict__ Q, const __half* __restrict__ Kp,
    const __half* __restrict__ V, float* __restrict__ Og)
{
    __shared__ __half Qs[256][QPAD];
    __shared__ __half Ks[128][QPAD];
    __shared__ __half VTs[32][VPAD];

    const int tid = threadIdx.x;
    const int w = tid >> 5, lane = tid & 31;
    const int g = lane >> 2, tc = lane & 3;
    const int hoff = blockIdx.y * DHH;
    const int q0 = blockIdx.x * 256;
    const __half2 qsc2 = __float2half2_rn(QSC);

    #pragma unroll
    for (int it = 0; it < 16; it++) {
        int idx = it*256 + tid;
        int r = idx >> 4, pr = idx & 15;
        __half2 h2 = *(const __half2*)&Q[(q0 + r)*CC + hoff + pr*2];
        *(__half2*)&Qs[r][pr*2] = __hmul2(h2, qsc2);
    }
    __syncthreads();

    uint32_t qa[2][2][4];
    #pragma unroll
    for (int mt = 0; mt < 2; mt++) {
        #pragma unroll
        for (int kt = 0; kt < 2; kt++) {
            int r0 = w*32 + mt*16 + g;
            qa[mt][kt][0] = *(const uint32_t*)&Qs[r0    ][kt*16 + 2*tc    ];
            qa[mt][kt][1] = *(const uint32_t*)&Qs[r0 + 8][kt*16 + 2*tc    ];
            qa[mt][kt][2] = *(const uint32_t*)&Qs[r0    ][kt*16 + 2*tc + 8];
            qa[mt][kt][3] = *(const uint32_t*)&Qs[r0 + 8][kt*16 + 2*tc + 8];
        }
    }

    float oacc[2][4][4] = {};
    float lacc[4] = {};
    float mrow[4] = {-1e30f, -1e30f, -1e30f, -1e30f};

    for (int j0 = 0; j0 < NN; j0 += 128) {
        __syncthreads();
        #pragma unroll
        for (int it = 0; it < 8; it++) {
            int idx = it*256 + tid;
            int r = idx >> 4, pr = idx & 15;
            *(uint32_t*)&Ks[r][pr*2] = *(const uint32_t*)&Kp[(j0 + r)*CC + hoff + pr*2];
        }
        #pragma unroll
        for (int it = 0; it < 8; it++) {
            int idx = it*256 + tid;
            int j = idx >> 4, dp = idx & 15;
            __half2 h2 = *(const __half2*)&V[(j0 + j)*CC + hoff + dp*2];
            VTs[dp*2    ][j] = __low2half(h2);
            VTs[dp*2 + 1][j] = __high2half(h2);
        }
        __syncthreads();

        #pragma unroll
        for (int ng = 0; ng < 8; ng++) {
            const int kb = ng*16;
            float s[2][2][4] = {};
            #pragma unroll
            for (int kt = 0; kt < 2; kt++) {
                uint32_t b[2][2];
                #pragma unroll
                for (int j = 0; j < 2; j++) {
                    int key = kb + j*8 + g;
                    b[j][0] = *(const uint32_t*)&Ks[key][kt*16 + 2*tc    ];
                    b[j][1] = *(const uint32_t*)&Ks[key][kt*16 + 2*tc + 8];
                }
                #pragma unroll
                for (int mt = 0; mt < 2; mt++)
                    #pragma unroll
                    for (int j = 0; j < 2; j++)
                        mma16816(s[mt][j], qa[mt][kt], b[j]);
            }
            uint32_t pa[2][4];
            #pragma unroll
            for (int mt = 0; mt < 2; mt++) {
                #pragma unroll
                for (int hi = 0; hi < 2; hi++) {
                    float rm = fmaxf(fmaxf(s[mt][0][2*hi], s[mt][0][2*hi+1]),
                                     fmaxf(s[mt][1][2*hi], s[mt][1][2*hi+1]));
                    rm = fmaxf(rm, __shfl_xor_sync(0xffffffffu, rm, 1));
                    rm = fmaxf(rm, __shfl_xor_sync(0xffffffffu, rm, 2));
                    float mold = mrow[mt*2 + hi];
                    float mnew = fmaxf(mold, rm);
                    float p00 = ex2(s[mt][0][2*hi]   - mnew);
                    float p01 = ex2(s[mt][0][2*hi+1] - mnew);
                    float p10 = ex2(s[mt][1][2*hi]   - mnew);
                    float p11 = ex2(s[mt][1][2*hi+1] - mnew);
                    float psum = p00 + p01 + p10 + p11;
                    if (rm > mold) {
                        float cf = ex2(mold - mnew);
                        mrow[mt*2 + hi] = mnew;
                        lacc[mt*2 + hi] = lacc[mt*2 + hi]*cf + psum;
                        #pragma unroll
                        for (int dj = 0; dj < 4; dj++) {
                            oacc[mt][dj][2*hi]   *= cf;
                            oacc[mt][dj][2*hi+1] *= cf;
                        }
                    } else {
                        lacc[mt*2 + hi] += psum;
                    }
                    pa[mt][0*2 + hi] = packh2(p00, p01);
                    pa[mt][1*2 + hi] = packh2(p10, p11);
                }
            }
            #pragma unroll
            for (int dj = 0; dj < 4; dj++) {
                uint32_t vb[2];
                vb[0] = *(const uint32_t*)&VTs[dj*8 + g][kb + 2*tc    ];
                vb[1] = *(const uint32_t*)&VTs[dj*8 + g][kb + 2*tc + 8];
                #pragma unroll
                for (int mt = 0; mt < 2; mt++)
                    mma16816(oacc[mt][dj], pa[mt], vb);
            }
        }
    }

    #pragma unroll
    for (int i = 0; i < 4; i++) {
        lacc[i] += __shfl_xor_sync(0xffffffffu, lacc[i], 1);
        lacc[i] += __shfl_xor_sync(0xffffffffu, lacc[i], 2);
    }
    #pragma unroll
    for (int mt = 0; mt < 2; mt++) {
        int rbase = q0 + w*32 + mt*16;
        float inv0 = 1.f / lacc[mt*2 + 0];
        float inv1 = 1.f / lacc[mt*2 + 1];
        #pragma unroll
        for (int dj = 0; dj < 4; dj++) {
            int col = hoff + dj*8 + 2*tc;
            *(float2*)&Og[(rbase + g    )*CC + col] =
                make_float2(oacc[mt][dj][0]*inv0, oacc[mt][dj][1]*inv0);
            *(float2*)&Og[(rbase + g + 8)*CC + col] =
                make_float2(oacc[mt][dj][2]*inv1, oacc[mt][dj][3]*inv1);
        }
    }
}

// ---------------- small kernels ----------------
__global__ void lin1_kernel(const float* __restrict__ x, const float* __restrict__ w,
                            const float* __restrict__ b) {
    int n = blockIdx.x, c = threadIdx.x;
    g_h[n*CC + c] = x[n]*w[c] + b[c];
}

__global__ void zero_kernel(float* __restrict__ p, int n) {
    int i = blockIdx.x*blockDim.x + threadIdx.x;
    if (i < n) p[i] = 0.f;
}

__global__ void zero_stats_kernel() {
    int i = blockIdx.x*256 + threadIdx.x;
    g_sum[i] = 0.f;
    g_sumsq[i] = 0.f;
    if (blockIdx.x == 0 && threadIdx.x < 9) g_cnt[threadIdx.x] = 0;
}

__global__ void scatter_kernel(const int* __restrict__ ei, int E) {
    const int* src = ei;
    const int* dst = ei + E;
    int e = blockIdx.x*4 + (threadIdx.x >> 6);
    int c4 = (threadIdx.x & 63) * 4;
    int s = src[e], d = dst[e];
    float4 val = *(const float4*)&g_h[s*CC + c4];
    float* p = &g_agg[d*CC + c4];
    asm volatile("red.global.add.v4.f32 [%0], {%1, %2, %3, %4};"
                 :: "l"(p), "f"(val.x), "f"(val.y), "f"(val.z), "f"(val.w)
                 : "memory");
}

// ---------------- fused BN: stats + grid-sync + apply ----------------
__global__ void __launch_bounds__(256) bn_fused_kernel(
    const float* __restrict__ in1, const float* __restrict__ in2,
    int slot,
    const float* __restrict__ gamma, const float* __restrict__ beta,
    const float* __restrict__ addend, float* __restrict__ out)
{
    const int c = threadIdx.x;
    const int r0 = blockIdx.x * 32;
    const int statoff = slot * CC;

    float v[32];
    float s = 0.f, ss = 0.f;
    #pragma unroll 4
    for (int i = 0; i < 32; i++) {
        float x = in1[(r0 + i)*CC + c] + in2[(r0 + i)*CC + c];
        v[i] = x;
        s += x; ss += x*x;
    }
    atomicAdd(&g_sum[statoff + c], s);
    atomicAdd(&g_sumsq[statoff + c], ss);
    __threadfence();
    __syncthreads();
    if (threadIdx.x == 0) atomicAdd(&g_cnt[slot], 1);
    if (threadIdx.x == 0) {
        while (atomicAdd(&g_cnt[slot], 0) < (int)gridDim.x) { }
    }
    __syncthreads();

    float mean = g_sum[statoff + c] * (1.f/NN);
    float var  = g_sumsq[statoff + c] * (1.f/NN) - mean*mean;
    float scale = rsqrtf(var + EPSV) * gamma[c];
    float shift = beta[c] - mean * scale;
    #pragma unroll 4
    for (int i = 0; i < 32; i++) {
        float r = v[i] * scale + shift;
        if (addend) r += addend[(r0 + i)*CC + c];
        out[(r0 + i)*CC + c] = r;
    }
}

// ---------------- host ----------------
extern "C" void kernel_launch(void* const* d_in, const int* in_sizes, int n_in,
                              void* d_out, int out_size) {
    const float* x      = (const float*)d_in[0];
    const int*   ei     = (const int*)  d_in[1];
    const float* lin1_w = (const float*)d_in[2];
    const float* lin1_b = (const float*)d_in[3];
    const float* gin_b1 = (const float*)d_in[5];
    const float* gin_b2 = (const float*)d_in[7];
    const float* bq = (const float*)d_in[12];
    const float* bk = (const float*)d_in[13];
    const float* bv = (const float*)d_in[14];
    const float* bo = (const float*)d_in[15];
    const float* bn1_g = (const float*)d_in[16];
    const float* bn1_b = (const float*)d_in[17];
    const float* bn2_g = (const float*)d_in[18];
    const float* bn2_b = (const float*)d_in[19];
    const float* bn3_g = (const float*)d_in[20];
    const float* bn3_b = (const float*)d_in[21];
    const float* mb1 = (const float*)d_in[23];
    const float* mb2 = (const float*)d_in[25];
    int E = in_sizes[1] / 2;

    float *h, *agg, *t1, *t2, *q, *t3, *o, *h1;
    cudaGetSymbolAddress((void**)&h,   g_h);
    cudaGetSymbolAddress((void**)&agg, g_agg);
    cudaGetSymbolAddress((void**)&t1,  g_t1);
    cudaGetSymbolAddress((void**)&t2,  g_t2);
    cudaGetSymbolAddress((void**)&q,   g_q);
    cudaGetSymbolAddress((void**)&t3,  g_t3);
    cudaGetSymbolAddress((void**)&o,   g_o);
    cudaGetSymbolAddress((void**)&h1,  g_h1);
    __half *wh, *wl, *qh, *kh, *vh;
    cudaGetSymbolAddress((void**)&wh, g_wh);
    cudaGetSymbolAddress((void**)&wl, g_wl);
    cudaGetSymbolAddress((void**)&qh, g_qh);
    cudaGetSymbolAddress((void**)&kh, g_kh);
    cudaGetSymbolAddress((void**)&vh, g_vh);

    convw_all_kernel<<<(TOTW + 255)/256, 256>>>(
        (const float*)d_in[4], (const float*)d_in[6],
        (const float*)d_in[8], (const float*)d_in[9],
        (const float*)d_in[10], (const float*)d_in[11],
        (const float*)d_in[22], (const float*)d_in[24]);
    zero_stats_kernel<<<9, 256>>>();

    dim3 gN256(CC/64,   NN/128);
    dim3 gN512(2*CC/64, NN/128);
    dim3 gqkv (CC/64,   NN/128, 3);
    int ewgrid = NN*CC/256;

    lin1_kernel<<<NN, CC>>>(x, lin1_w, lin1_b);

    for (int l = 0; l < LL; l++) {
        int w1 = l*CC*CC, w2 = l*2*CC*CC;
        int sl = l*3;
        // ---- GIN branch ----
        zero_kernel<<<ewgrid, 256>>>(agg, NN*CC);
        scatter_kernel<<<E/4, 256>>>(ei, E);
        gemm_mma_kernel<<<gN256, 128>>>(h, agg, wh + OFF_GW1 + w1, wl + OFF_GW1 + w1,
                                        gin_b1 + l*CC, t1, CC, CC, 1);
        gemm_mma_kernel<<<gN256, 128>>>(t1, nullptr, wh + OFF_GW2 + w1, wl + OFF_GW2 + w1,
                                        gin_b2 + l*CC, t2, CC, CC, 0);
        bn_fused_kernel<<<128, 256>>>(t2, h, sl, bn1_g + l*CC, bn1_b + l*CC, nullptr, h1);
        // ---- global attention ----
        qkv_mma_kernel<<<gqkv, 128>>>(h, wh, wl, bq + l*CC, bk + l*CC, bv + l*CC, l);
        flash_mma_kernel<<<dim3(NN/256, HH), 256>>>(qh, kh, vh, o);
        gemm_mma_kernel<<<gN256, 128>>>(o, nullptr, wh + OFF_WO + w1, wl + OFF_WO + w1,
                                        bo + l*CC, t3, CC, CC, 0);
        bn_fused_kernel<<<128, 256>>>(t3, h, sl + 1, bn2_g + l*CC, bn2_b + l*CC, h1, q);
        // ---- feedforward ----
        gemm_mma_kernel<<<gN512, 128>>>(q, nullptr, wh + OFF_MW1 + w2, wl + OFF_MW1 + w2,
                                        mb1 + l*2*CC, t1, 2*CC, CC, 1);
        gemm_mma_kernel<<<gN256, 128>>>(t1, nullptr, wh + OFF_MW2 + w2, wl + OFF_MW2 + w2,
                                        mb2 + l*CC, t2, CC, 2*CC, 0);
        bn_fused_kernel<<<128, 256>>>(t2, q, sl + 2, bn3_g + l*CC, bn3_b + l*CC, nullptr,
                                      (l == LL-1) ? (float*)d_out : h);
    }
    (void)n_in; (void)out_size;
}

// round 16
// speedup vs baseline: 1.1656x; 1.0323x over previous
#include <cuda_runtime.h>
#include <cuda_fp16.h>
#include <math.h>
#include <stdint.h>

#define NN 4096
#define CC 256
#define HH 8
#define DHH 32
#define LL 3
#define EPSV 1e-5f
#define QSC (0.17677669529663687f * 1.4426950408889634f)

// ---------------- scratch (no allocation allowed) ----------------
__device__ float g_h[NN*CC];
__device__ float g_agg[NN*CC];
__device__ float g_t1[NN*2*CC];
__device__ float g_t2[NN*CC];
__device__ float g_q[NN*CC];
__device__ float g_t3[NN*CC];
__device__ float g_o[NN*CC];
__device__ float g_h1[NN*CC];
__device__ __half g_qh[NN*CC];
__device__ __half g_kh[NN*CC];
__device__ __half g_vh[NN*CC];
__device__ float g_sum[9*CC];
__device__ float g_sumsq[9*CC];
__device__ int   g_cnt[9];
// CSR of incoming edges
#define EMAX 65536
__device__ int g_deg[NN];
__device__ int g_cur[NN];
__device__ int g_cs[NN + 1];
__device__ int g_srcl[EMAX];

// fp16 hi/lo weight cache
#define OFF_GW1 0
#define OFF_GW2 196608
#define OFF_WQ  393216
#define OFF_WK  589824
#define OFF_WV  786432
#define OFF_WO  983040
#define OFF_MW1 1179648
#define OFF_MW2 1572864
#define TOTW    1966080
__device__ __half g_wh[TOTW];
__device__ __half g_wl[TOTW];

// ---------------- helpers ----------------
__device__ __forceinline__ void mma16816(float* d, const uint32_t* a, const uint32_t* b) {
    asm volatile(
        "mma.sync.aligned.m16n8k16.row.col.f32.f16.f16.f32 "
        "{%0,%1,%2,%3}, {%4,%5,%6,%7}, {%8,%9}, {%0,%1,%2,%3};"
        : "+f"(d[0]), "+f"(d[1]), "+f"(d[2]), "+f"(d[3])
        : "r"(a[0]), "r"(a[1]), "r"(a[2]), "r"(a[3]), "r"(b[0]), "r"(b[1]));
}
__device__ __forceinline__ uint32_t packh2(float x, float y) {
    __half2 h = __floats2half2_rn(x, y);
    return *(uint32_t*)&h;
}
__device__ __forceinline__ float ex2(float x) {
    float r;
    asm("ex2.approx.ftz.f32 %0, %1;" : "=f"(r) : "f"(x));
    return r;
}

// ---------------- weight conversion ----------------
__global__ void convw_all_kernel(
    const float* __restrict__ gw1, const float* __restrict__ gw2,
    const float* __restrict__ wq,  const float* __restrict__ wk,
    const float* __restrict__ wv,  const float* __restrict__ wo,
    const float* __restrict__ mw1, const float* __restrict__ mw2)
{
    int i = blockIdx.x*256 + threadIdx.x;
    if (i >= TOTW) return;
    const float* src; int off;
    if      (i < OFF_GW2) { src = gw1; off = OFF_GW1; }
    else if (i < OFF_WQ)  { src = gw2; off = OFF_GW2; }
    else if (i < OFF_WK)  { src = wq;  off = OFF_WQ;  }
    else if (i < OFF_WV)  { src = wk;  off = OFF_WK;  }
    else if (i < OFF_WO)  { src = wv;  off = OFF_WV;  }
    else if (i < OFF_MW1) { src = wo;  off = OFF_WO;  }
    else if (i < OFF_MW2) { src = mw1; off = OFF_MW1; }
    else                  { src = mw2; off = OFF_MW2; }
    float x = src[i - off];
    __half h = __float2half_rn(x);
    g_wh[i] = h;
    g_wl[i] = __float2half_rn(x - __half2float(h));
}

// ---------------- CSR build (per launch; graph is a kernel input) ----------------
__global__ void csr_zero_kernel() {
    int i = blockIdx.x*256 + threadIdx.x;
    if (i < NN) { g_deg[i] = 0; g_cur[i] = 0; }
}
__global__ void csr_hist_kernel(const int* __restrict__ ei, int E) {
    int e = blockIdx.x*256 + threadIdx.x;
    if (e < E) atomicAdd(&g_deg[ei[E + e]], 1);
}
// exclusive scan over NN=4096 degrees, single block of 1024 (4 elems/thread)
__global__ void __launch_bounds__(1024) csr_scan_kernel() {
    __shared__ int s[1024];
    int t = threadIdx.x;
    int v0 = g_deg[t*4], v1 = g_deg[t*4+1], v2 = g_deg[t*4+2], v3 = g_deg[t*4+3];
    int loc = v0 + v1 + v2 + v3;
    s[t] = loc;
    __syncthreads();
    // Hillis-Steele inclusive scan
    for (int off = 1; off < 1024; off <<= 1) {
        int x = (t >= off) ? s[t - off] : 0;
        __syncthreads();
        s[t] += x;
        __syncthreads();
    }
    int base = s[t] - loc;   // exclusive prefix for this thread's group
    g_cs[t*4]   = base;
    g_cs[t*4+1] = base + v0;
    g_cs[t*4+2] = base + v0 + v1;
    g_cs[t*4+3] = base + v0 + v1 + v2;
    if (t == 1023) g_cs[NN] = s[1023];
}
__global__ void csr_fill_kernel(const int* __restrict__ ei, int E) {
    int e = blockIdx.x*256 + threadIdx.x;
    if (e < E) {
        int d = ei[E + e];
        int pos = atomicAdd(&g_cur[d], 1);
        g_srcl[g_cs[d] + pos] = ei[e];
    }
}

// ---------------- gather aggregation: agg[n] = sum_{s in in(n)} h[s] ----------------
// block = 256 threads = 4 nodes x 64 threads; thread owns 4 channels.
__global__ void __launch_bounds__(256) gather_kernel() {
    int node = blockIdx.x*4 + (threadIdx.x >> 6);
    int c4 = (threadIdx.x & 63) * 4;
    int beg = g_cs[node], end = g_cs[node + 1];
    float4 acc = make_float4(0.f, 0.f, 0.f, 0.f);
    for (int i = beg; i < end; i++) {
        int s = g_srcl[i];
        float4 v = *(const float4*)&g_h[s*CC + c4];
        acc.x += v.x; acc.y += v.y; acc.z += v.z; acc.w += v.w;
    }
    *(float4*)&g_agg[node*CC + c4] = acc;
}

// ---------------- HMMA GEMM (3-term hi/lo split); OUTHALF selects fp16 output ----------------
#define APAD 40
template<bool OUTHALF>
__device__ __forceinline__ void gemm_mma_body(
    const float* __restrict__ A1, const float* __restrict__ A2,
    const __half* __restrict__ Bh, const __half* __restrict__ Bl,
    const float* __restrict__ bias, void* __restrict__ Cv,
    int Nout, int K, int relu, int m0, int n0)
{
    __shared__ __half Ah[128][APAD];
    __shared__ __half Al[128][APAD];
    __shared__ __half Bhs[64][APAD];
    __shared__ __half Bls[64][APAD];

    const int tid = threadIdx.x;
    const int w = tid >> 5, lane = tid & 31;
    const int g = lane >> 2, tc = lane & 3;
    const int wm = w & 1, wn = w >> 1;

    float acc[4][4][4] = {};

    for (int k0 = 0; k0 < K; k0 += 32) {
        #pragma unroll
        for (int it = 0; it < 16; it++) {
            int idx = it*128 + tid;
            int r = idx >> 4, c2 = idx & 15;
            const float* p = &A1[(m0 + r)*K + k0 + c2*2];
            float ax = p[0], ay = p[1];
            if (A2) { const float* p2 = &A2[(m0 + r)*K + k0 + c2*2]; ax += p2[0]; ay += p2[1]; }
            __half hx = __float2half_rn(ax), hy = __float2half_rn(ay);
            Ah[r][c2*2]   = hx; Ah[r][c2*2+1] = hy;
            Al[r][c2*2]   = __float2half_rn(ax - __half2float(hx));
            Al[r][c2*2+1] = __float2half_rn(ay - __half2float(hy));
        }
        #pragma unroll
        for (int it = 0; it < 8; it++) {
            int idx = it*128 + tid;
            int r = idx >> 4, c2 = idx & 15;
            *(__half2*)&Bhs[r][c2*2] = *(const __half2*)&Bh[(n0 + r)*K + k0 + c2*2];
            *(__half2*)&Bls[r][c2*2] = *(const __half2*)&Bl[(n0 + r)*K + k0 + c2*2];
        }
        __syncthreads();

        #pragma unroll
        for (int kt = 0; kt < 2; kt++) {
            uint32_t ah[4][4], al[4][4], bh[4][2], bl[4][2];
            #pragma unroll
            for (int mt = 0; mt < 4; mt++) {
                int rb = wm*64 + mt*16 + g;
                int c = kt*16 + 2*tc;
                ah[mt][0] = *(const uint32_t*)&Ah[rb    ][c];
                ah[mt][1] = *(const uint32_t*)&Ah[rb + 8][c];
                ah[mt][2] = *(const uint32_t*)&Ah[rb    ][c + 8];
                ah[mt][3] = *(const uint32_t*)&Ah[rb + 8][c + 8];
                al[mt][0] = *(const uint32_t*)&Al[rb    ][c];
                al[mt][1] = *(const uint32_t*)&Al[rb + 8][c];
                al[mt][2] = *(const uint32_t*)&Al[rb    ][c + 8];
                al[mt][3] = *(const uint32_t*)&Al[rb + 8][c + 8];
            }
            #pragma unroll
            for (int nt = 0; nt < 4; nt++) {
                int nb = wn*32 + nt*8 + g;
                int c = kt*16 + 2*tc;
                bh[nt][0] = *(const uint32_t*)&Bhs[nb][c];
                bh[nt][1] = *(const uint32_t*)&Bhs[nb][c + 8];
                bl[nt][0] = *(const uint32_t*)&Bls[nb][c];
                bl[nt][1] = *(const uint32_t*)&Bls[nb][c + 8];
            }
            #pragma unroll
            for (int mt = 0; mt < 4; mt++)
                #pragma unroll
                for (int nt = 0; nt < 4; nt++) {
                    mma16816(acc[mt][nt], ah[mt], bh[nt]);
                    mma16816(acc[mt][nt], al[mt], bh[nt]);
                    mma16816(acc[mt][nt], ah[mt], bl[nt]);
                }
        }
        __syncthreads();
    }

    #pragma unroll
    for (int mt = 0; mt < 4; mt++) {
        int row = m0 + wm*64 + mt*16 + g;
        #pragma unroll
        for (int nt = 0; nt < 4; nt++) {
            int col = n0 + wn*32 + nt*8 + 2*tc;
            float b0 = bias[col], b1 = bias[col + 1];
            float v0 = acc[mt][nt][0] + b0, v1 = acc[mt][nt][1] + b1;
            float v2 = acc[mt][nt][2] + b0, v3 = acc[mt][nt][3] + b1;
            if (relu) {
                v0 = fmaxf(v0, 0.f); v1 = fmaxf(v1, 0.f);
                v2 = fmaxf(v2, 0.f); v3 = fmaxf(v3, 0.f);
            }
            if (OUTHALF) {
                __half* C = (__half*)Cv;
                *(__half2*)&C[row*Nout + col]       = __floats2half2_rn(v0, v1);
                *(__half2*)&C[(row + 8)*Nout + col] = __floats2half2_rn(v2, v3);
            } else {
                float* C = (float*)Cv;
                *(float2*)&C[row*Nout + col]       = make_float2(v0, v1);
                *(float2*)&C[(row + 8)*Nout + col] = make_float2(v2, v3);
            }
        }
    }
}

__global__ void __launch_bounds__(128) gemm_mma_kernel(
    const float* __restrict__ A1, const float* __restrict__ A2,
    const __half* __restrict__ Bh, const __half* __restrict__ Bl,
    const float* __restrict__ bias, float* __restrict__ C,
    int Nout, int K, int relu)
{
    gemm_mma_body<false>(A1, A2, Bh, Bl, bias, C, Nout, K, relu,
                         blockIdx.y*128, blockIdx.x*64);
}

__global__ void __launch_bounds__(128) qkv_mma_kernel(
    const float* __restrict__ A, const __half* __restrict__ wh,
    const __half* __restrict__ wl,
    const float* __restrict__ bq, const float* __restrict__ bk,
    const float* __restrict__ bv, int l)
{
    const __half *Bh, *Bl; const float* bias; __half* C;
    int woff = l*CC*CC;
    if (blockIdx.z == 0)      { Bh = wh + OFF_WQ + woff; Bl = wl + OFF_WQ + woff; bias = bq; C = g_qh; }
    else if (blockIdx.z == 1) { Bh = wh + OFF_WK + woff; Bl = wl + OFF_WK + woff; bias = bk; C = g_kh; }
    else                      { Bh = wh + OFF_WV + woff; Bl = wl + OFF_WV + woff; bias = bv; C = g_vh; }
    gemm_mma_body<true>(A, nullptr, Bh, Bl, bias, C, CC, CC, 0,
                        blockIdx.y*128, blockIdx.x*64);
}

// ---------------- flash attention (fp16 in gmem, fp16 mma, online softmax) ----------------
#define QPAD 36
#define VPAD 132
__global__ void __launch_bounds__(256) flash_mma_kernel(
    const __half* __restrict__ Q, const __half* __restrict__ Kp,
    const __half* __restrict__ V, float* __restrict__ Og)
{
    __shared__ __half Qs[256][QPAD];
    __shared__ __half Ks[128][QPAD];
    __shared__ __half VTs[32][VPAD];

    const int tid = threadIdx.x;
    const int w = tid >> 5, lane = tid & 31;
    const int g = lane >> 2, tc = lane & 3;
    const int hoff = blockIdx.y * DHH;
    const int q0 = blockIdx.x * 256;
    const __half2 qsc2 = __float2half2_rn(QSC);

    #pragma unroll
    for (int it = 0; it < 16; it++) {
        int idx = it*256 + tid;
        int r = idx >> 4, pr = idx & 15;
        __half2 h2 = *(const __half2*)&Q[(q0 + r)*CC + hoff + pr*2];
        *(__half2*)&Qs[r][pr*2] = __hmul2(h2, qsc2);
    }
    __syncthreads();

    uint32_t qa[2][2][4];
    #pragma unroll
    for (int mt = 0; mt < 2; mt++) {
        #pragma unroll
        for (int kt = 0; kt < 2; kt++) {
            int r0 = w*32 + mt*16 + g;
            qa[mt][kt][0] = *(const uint32_t*)&Qs[r0    ][kt*16 + 2*tc    ];
            qa[mt][kt][1] = *(const uint32_t*)&Qs[r0 + 8][kt*16 + 2*tc    ];
            qa[mt][kt][2] = *(const uint32_t*)&Qs[r0    ][kt*16 + 2*tc + 8];
            qa[mt][kt][3] = *(const uint32_t*)&Qs[r0 + 8][kt*16 + 2*tc + 8];
        }
    }

    float oacc[2][4][4] = {};
    float lacc[4] = {};
    float mrow[4] = {-1e30f, -1e30f, -1e30f, -1e30f};

    for (int j0 = 0; j0 < NN; j0 += 128) {
        __syncthreads();
        #pragma unroll
        for (int it = 0; it < 8; it++) {
            int idx = it*256 + tid;
            int r = idx >> 4, pr = idx & 15;
            *(uint32_t*)&Ks[r][pr*2] = *(const uint32_t*)&Kp[(j0 + r)*CC + hoff + pr*2];
        }
        #pragma unroll
        for (int it = 0; it < 8; it++) {
            int idx = it*256 + tid;
            int j = idx >> 4, dp = idx & 15;
            __half2 h2 = *(const __half2*)&V[(j0 + j)*CC + hoff + dp*2];
            VTs[dp*2    ][j] = __low2half(h2);
            VTs[dp*2 + 1][j] = __high2half(h2);
        }
        __syncthreads();

        #pragma unroll
        for (int ng = 0; ng < 8; ng++) {
            const int kb = ng*16;
            float s[2][2][4] = {};
            #pragma unroll
            for (int kt = 0; kt < 2; kt++) {
                uint32_t b[2][2];
                #pragma unroll
                for (int j = 0; j < 2; j++) {
                    int key = kb + j*8 + g;
                    b[j][0] = *(const uint32_t*)&Ks[key][kt*16 + 2*tc    ];
                    b[j][1] = *(const uint32_t*)&Ks[key][kt*16 + 2*tc + 8];
                }
                #pragma unroll
                for (int mt = 0; mt < 2; mt++)
                    #pragma unroll
                    for (int j = 0; j < 2; j++)
                        mma16816(s[mt][j], qa[mt][kt], b[j]);
            }
            uint32_t pa[2][4];
            #pragma unroll
            for (int mt = 0; mt < 2; mt++) {
                #pragma unroll
                for (int hi = 0; hi < 2; hi++) {
                    float rm = fmaxf(fmaxf(s[mt][0][2*hi], s[mt][0][2*hi+1]),
                                     fmaxf(s[mt][1][2*hi], s[mt][1][2*hi+1]));
                    rm = fmaxf(rm, __shfl_xor_sync(0xffffffffu, rm, 1));
                    rm = fmaxf(rm, __shfl_xor_sync(0xffffffffu, rm, 2));
                    float mold = mrow[mt*2 + hi];
                    float mnew = fmaxf(mold, rm);
                    float p00 = ex2(s[mt][0][2*hi]   - mnew);
                    float p01 = ex2(s[mt][0][2*hi+1] - mnew);
                    float p10 = ex2(s[mt][1][2*hi]   - mnew);
                    float p11 = ex2(s[mt][1][2*hi+1] - mnew);
                    float psum = p00 + p01 + p10 + p11;
                    if (rm > mold) {
                        float cf = ex2(mold - mnew);
                        mrow[mt*2 + hi] = mnew;
                        lacc[mt*2 + hi] = lacc[mt*2 + hi]*cf + psum;
                        #pragma unroll
                        for (int dj = 0; dj < 4; dj++) {
                            oacc[mt][dj][2*hi]   *= cf;
                            oacc[mt][dj][2*hi+1] *= cf;
                        }
                    } else {
                        lacc[mt*2 + hi] += psum;
                    }
                    pa[mt][0*2 + hi] = packh2(p00, p01);
                    pa[mt][1*2 + hi] = packh2(p10, p11);
                }
            }
            #pragma unroll
            for (int dj = 0; dj < 4; dj++) {
                uint32_t vb[2];
                vb[0] = *(const uint32_t*)&VTs[dj*8 + g][kb + 2*tc    ];
                vb[1] = *(const uint32_t*)&VTs[dj*8 + g][kb + 2*tc + 8];
                #pragma unroll
                for (int mt = 0; mt < 2; mt++)
                    mma16816(oacc[mt][dj], pa[mt], vb);
            }
        }
    }

    #pragma unroll
    for (int i = 0; i < 4; i++) {
        lacc[i] += __shfl_xor_sync(0xffffffffu, lacc[i], 1);
        lacc[i] += __shfl_xor_sync(0xffffffffu, lacc[i], 2);
    }
    #pragma unroll
    for (int mt = 0; mt < 2; mt++) {
        int rbase = q0 + w*32 + mt*16;
        float inv0 = 1.f / lacc[mt*2 + 0];
        float inv1 = 1.f / lacc[mt*2 + 1];
        #pragma unroll
        for (int dj = 0; dj < 4; dj++) {
            int col = hoff + dj*8 + 2*tc;
            *(float2*)&Og[(rbase + g    )*CC + col] =
                make_float2(oacc[mt][dj][0]*inv0, oacc[mt][dj][1]*inv0);
            *(float2*)&Og[(rbase + g + 8)*CC + col] =
                make_float2(oacc[mt][dj][2]*inv1, oacc[mt][dj][3]*inv1);
        }
    }
}

// ---------------- small kernels ----------------
__global__ void lin1_kernel(const float* __restrict__ x, const float* __restrict__ w,
                            const float* __restrict__ b) {
    int n = blockIdx.x, c = threadIdx.x;
    g_h[n*CC + c] = x[n]*w[c] + b[c];
}

__global__ void zero_stats_kernel() {
    int i = blockIdx.x*256 + threadIdx.x;
    g_sum[i] = 0.f;
    g_sumsq[i] = 0.f;
    if (blockIdx.x == 0 && threadIdx.x < 9) g_cnt[threadIdx.x] = 0;
}

// ---------------- fused BN: stats + grid-sync + apply ----------------
__global__ void __launch_bounds__(256) bn_fused_kernel(
    const float* __restrict__ in1, const float* __restrict__ in2,
    int slot,
    const float* __restrict__ gamma, const float* __restrict__ beta,
    const float* __restrict__ addend, float* __restrict__ out)
{
    const int c = threadIdx.x;
    const int r0 = blockIdx.x * 32;
    const int statoff = slot * CC;

    float v[32];
    float s = 0.f, ss = 0.f;
    #pragma unroll 4
    for (int i = 0; i < 32; i++) {
        float x = in1[(r0 + i)*CC + c] + in2[(r0 + i)*CC + c];
        v[i] = x;
        s += x; ss += x*x;
    }
    atomicAdd(&g_sum[statoff + c], s);
    atomicAdd(&g_sumsq[statoff + c], ss);
    __threadfence();
    __syncthreads();
    if (threadIdx.x == 0) atomicAdd(&g_cnt[slot], 1);
    if (threadIdx.x == 0) {
        while (atomicAdd(&g_cnt[slot], 0) < (int)gridDim.x) { }
    }
    __syncthreads();

    float mean = g_sum[statoff + c] * (1.f/NN);
    float var  = g_sumsq[statoff + c] * (1.f/NN) - mean*mean;
    float scale = rsqrtf(var + EPSV) * gamma[c];
    float shift = beta[c] - mean * scale;
    #pragma unroll 4
    for (int i = 0; i < 32; i++) {
        float r = v[i] * scale + shift;
        if (addend) r += addend[(r0 + i)*CC + c];
        out[(r0 + i)*CC + c] = r;
    }
}

// ---------------- host ----------------
extern "C" void kernel_launch(void* const* d_in, const int* in_sizes, int n_in,
                              void* d_out, int out_size) {
    const float* x      = (const float*)d_in[0];
    const int*   ei     = (const int*)  d_in[1];
    const float* lin1_w = (const float*)d_in[2];
    const float* lin1_b = (const float*)d_in[3];
    const float* gin_b1 = (const float*)d_in[5];
    const float* gin_b2 = (const float*)d_in[7];
    const float* bq = (const float*)d_in[12];
    const float* bk = (const float*)d_in[13];
    const float* bv = (const float*)d_in[14];
    const float* bo = (const float*)d_in[15];
    const float* bn1_g = (const float*)d_in[16];
    const float* bn1_b = (const float*)d_in[17];
    const float* bn2_g = (const float*)d_in[18];
    const float* bn2_b = (const float*)d_in[19];
    const float* bn3_g = (const float*)d_in[20];
    const float* bn3_b = (const float*)d_in[21];
    const float* mb1 = (const float*)d_in[23];
    const float* mb2 = (const float*)d_in[25];
    int E = in_sizes[1] / 2;

    float *h, *agg, *t1, *t2, *q, *t3, *o, *h1;
    cudaGetSymbolAddress((void**)&h,   g_h);
    cudaGetSymbolAddress((void**)&agg, g_agg);
    cudaGetSymbolAddress((void**)&t1,  g_t1);
    cudaGetSymbolAddress((void**)&t2,  g_t2);
    cudaGetSymbolAddress((void**)&q,   g_q);
    cudaGetSymbolAddress((void**)&t3,  g_t3);
    cudaGetSymbolAddress((void**)&o,   g_o);
    cudaGetSymbolAddress((void**)&h1,  g_h1);
    __half *wh, *wl, *qh, *kh, *vh;
    cudaGetSymbolAddress((void**)&wh, g_wh);
    cudaGetSymbolAddress((void**)&wl, g_wl);
    cudaGetSymbolAddress((void**)&qh, g_qh);
    cudaGetSymbolAddress((void**)&kh, g_kh);
    cudaGetSymbolAddress((void**)&vh, g_vh);

    convw_all_kernel<<<(TOTW + 255)/256, 256>>>(
        (const float*)d_in[4], (const float*)d_in[6],
        (const float*)d_in[8], (const float*)d_in[9],
        (const float*)d_in[10], (const float*)d_in[11],
        (const float*)d_in[22], (const float*)d_in[24]);
    zero_stats_kernel<<<9, 256>>>();
    // CSR build
    csr_zero_kernel<<<NN/256, 256>>>();
    csr_hist_kernel<<<(E + 255)/256, 256>>>(ei, E);
    csr_scan_kernel<<<1, 1024>>>();
    csr_fill_kernel<<<(E + 255)/256, 256>>>(ei, E);

    dim3 gN256(CC/64,   NN/128);
    dim3 gN512(2*CC/64, NN/128);
    dim3 gqkv (CC/64,   NN/128, 3);

    lin1_kernel<<<NN, CC>>>(x, lin1_w, lin1_b);

    for (int l = 0; l < LL; l++) {
        int w1 = l*CC*CC, w2 = l*2*CC*CC;
        int sl = l*3;
        // ---- GIN branch (CSR gather, no atomics, no zeroing) ----
        gather_kernel<<<NN/4, 256>>>();
        gemm_mma_kernel<<<gN256, 128>>>(h, agg, wh + OFF_GW1 + w1, wl + OFF_GW1 + w1,
                                        gin_b1 + l*CC, t1, CC, CC, 1);
        gemm_mma_kernel<<<gN256, 128>>>(t1, nullptr, wh + OFF_GW2 + w1, wl + OFF_GW2 + w1,
                                        gin_b2 + l*CC, t2, CC, CC, 0);
        bn_fused_kernel<<<128, 256>>>(t2, h, sl, bn1_g + l*CC, bn1_b + l*CC, nullptr, h1);
        // ---- global attention ----
        qkv_mma_kernel<<<gqkv, 128>>>(h, wh, wl, bq + l*CC, bk + l*CC, bv + l*CC, l);
        flash_mma_kernel<<<dim3(NN/256, HH), 256>>>(qh, kh, vh, o);
        gemm_mma_kernel<<<gN256, 128>>>(o, nullptr, wh + OFF_WO + w1, wl + OFF_WO + w1,
                                        bo + l*CC, t3, CC, CC, 0);
        bn_fused_kernel<<<128, 256>>>(t3, h, sl + 1, bn2_g + l*CC, bn2_b + l*CC, h1, q);
        // ---- feedforward ----
        gemm_mma_kernel<<<gN512, 128>>>(q, nullptr, wh + OFF_MW1 + w2, wl + OFF_MW1 + w2,
                                        mb1 + l*2*CC, t1, 2*CC, CC, 1);
        gemm_mma_kernel<<<gN256, 128>>>(t1, nullptr, wh + OFF_MW2 + w2, wl + OFF_MW2 + w2,
                                        mb2 + l*CC, t2, CC, 2*CC, 0);
        bn_fused_kernel<<<128, 256>>>(t2, q, sl + 2, bn3_g + l*CC, bn3_b + l*CC, nullptr,
                                      (l == LL-1) ? (float*)d_out : h);
    }
    (void)n_in; (void)out_size;
}

// round 17
// speedup vs baseline: 1.3404x; 1.1500x over previous
#include <cuda_runtime.h>
#include <cuda_fp16.h>
#include <math.h>
#include <stdint.h>

#define NN 4096
#define CC 256
#define HH 8
#define DHH 32
#define LL 3
#define EPSV 1e-5f
#define QSC (0.17677669529663687f * 1.4426950408889634f)

// ---------------- scratch (no allocation allowed) ----------------
__device__ float g_h[NN*CC];
__device__ float g_agg[NN*CC];
__device__ float g_t1[NN*2*CC];
__device__ float g_t2[NN*CC];
__device__ float g_q[NN*CC];
__device__ float g_t3[NN*CC];
__device__ float g_o[NN*CC];
__device__ float g_h1[NN*CC];
__device__ __half g_qh[NN*CC];
__device__ __half g_kh[NN*CC];
__device__ __half g_vh[NN*CC];
__device__ float g_sum[9*CC];
__device__ float g_sumsq[9*CC];
__device__ int   g_cnt[9];
// CSR of incoming edges
#define EMAX 65536
__device__ int g_deg[NN];
__device__ int g_cur[NN];
__device__ int g_cs[NN + 1];
__device__ int g_srcl[EMAX];

// fp16 hi/lo weight cache
#define OFF_GW1 0
#define OFF_GW2 196608
#define OFF_WQ  393216
#define OFF_WK  589824
#define OFF_WV  786432
#define OFF_WO  983040
#define OFF_MW1 1179648
#define OFF_MW2 1572864
#define TOTW    1966080
__device__ __half g_wh[TOTW];
__device__ __half g_wl[TOTW];

// ---------------- helpers ----------------
__device__ __forceinline__ void mma16816(float* d, const uint32_t* a, const uint32_t* b) {
    asm volatile(
        "mma.sync.aligned.m16n8k16.row.col.f32.f16.f16.f32 "
        "{%0,%1,%2,%3}, {%4,%5,%6,%7}, {%8,%9}, {%0,%1,%2,%3};"
        : "+f"(d[0]), "+f"(d[1]), "+f"(d[2]), "+f"(d[3])
        : "r"(a[0]), "r"(a[1]), "r"(a[2]), "r"(a[3]), "r"(b[0]), "r"(b[1]));
}
__device__ __forceinline__ uint32_t packh2(float x, float y) {
    __half2 h = __floats2half2_rn(x, y);
    return *(uint32_t*)&h;
}
__device__ __forceinline__ float ex2(float x) {
    float r;
    asm("ex2.approx.ftz.f32 %0, %1;" : "=f"(r) : "f"(x));
    return r;
}

// ---------------- weight conversion ----------------
__global__ void convw_all_kernel(
    const float* __restrict__ gw1, const float* __restrict__ gw2,
    const float* __restrict__ wq,  const float* __restrict__ wk,
    const float* __restrict__ wv,  const float* __restrict__ wo,
    const float* __restrict__ mw1, const float* __restrict__ mw2)
{
    int i = blockIdx.x*256 + threadIdx.x;
    if (i >= TOTW) return;
    const float* src; int off;
    if      (i < OFF_GW2) { src = gw1; off = OFF_GW1; }
    else if (i < OFF_WQ)  { src = gw2; off = OFF_GW2; }
    else if (i < OFF_WK)  { src = wq;  off = OFF_WQ;  }
    else if (i < OFF_WV)  { src = wk;  off = OFF_WK;  }
    else if (i < OFF_WO)  { src = wv;  off = OFF_WV;  }
    else if (i < OFF_MW1) { src = wo;  off = OFF_WO;  }
    else if (i < OFF_MW2) { src = mw1; off = OFF_MW1; }
    else                  { src = mw2; off = OFF_MW2; }
    float x = src[i - off];
    __half h = __float2half_rn(x);
    g_wh[i] = h;
    g_wl[i] = __float2half_rn(x - __half2float(h));
}

// ---------------- CSR build ----------------
__global__ void csr_zero_kernel() {
    int i = blockIdx.x*256 + threadIdx.x;
    if (i < NN) { g_deg[i] = 0; g_cur[i] = 0; }
}
__global__ void csr_hist_kernel(const int* __restrict__ ei, int E) {
    int e = blockIdx.x*256 + threadIdx.x;
    if (e < E) atomicAdd(&g_deg[ei[E + e]], 1);
}
__global__ void __launch_bounds__(1024) csr_scan_kernel() {
    __shared__ int s[1024];
    int t = threadIdx.x;
    int v0 = g_deg[t*4], v1 = g_deg[t*4+1], v2 = g_deg[t*4+2], v3 = g_deg[t*4+3];
    int loc = v0 + v1 + v2 + v3;
    s[t] = loc;
    __syncthreads();
    for (int off = 1; off < 1024; off <<= 1) {
        int x = (t >= off) ? s[t - off] : 0;
        __syncthreads();
        s[t] += x;
        __syncthreads();
    }
    int base = s[t] - loc;
    g_cs[t*4]   = base;
    g_cs[t*4+1] = base + v0;
    g_cs[t*4+2] = base + v0 + v1;
    g_cs[t*4+3] = base + v0 + v1 + v2;
    if (t == 1023) g_cs[NN] = s[1023];
}
__global__ void csr_fill_kernel(const int* __restrict__ ei, int E) {
    int e = blockIdx.x*256 + threadIdx.x;
    if (e < E) {
        int d = ei[E + e];
        int pos = atomicAdd(&g_cur[d], 1);
        g_srcl[g_cs[d] + pos] = ei[e];
    }
}

// ---------------- gather aggregation ----------------
__global__ void __launch_bounds__(256) gather_kernel() {
    int node = blockIdx.x*4 + (threadIdx.x >> 6);
    int c4 = (threadIdx.x & 63) * 4;
    int beg = g_cs[node], end = g_cs[node + 1];
    float4 acc = make_float4(0.f, 0.f, 0.f, 0.f);
    for (int i = beg; i < end; i++) {
        int s = g_srcl[i];
        float4 v = *(const float4*)&g_h[s*CC + c4];
        acc.x += v.x; acc.y += v.y; acc.z += v.z; acc.w += v.w;
    }
    *(float4*)&g_agg[node*CC + c4] = acc;
}

// ---------------- HMMA GEMM (3-term hi/lo split), register-prefetch pipelined ----------------
#define APAD 40
template<bool OUTHALF>
__device__ __forceinline__ void gemm_mma_body(
    const float* __restrict__ A1, const float* __restrict__ A2,
    const __half* __restrict__ Bh, const __half* __restrict__ Bl,
    const float* __restrict__ bias, void* __restrict__ Cv,
    int Nout, int K, int relu, int m0, int n0)
{
    __shared__ __half Ah[128][APAD];
    __shared__ __half Al[128][APAD];
    __shared__ __half Bhs[64][APAD];
    __shared__ __half Bls[64][APAD];

    const int tid = threadIdx.x;
    const int w = tid >> 5, lane = tid & 31;
    const int g = lane >> 2, tc = lane & 3;
    const int wm = w & 1, wn = w >> 1;

    // per-thread staging coordinates
    const int arr = tid >> 4,        ac2 = tid & 15;       // A: rows arr, arr+8, ... (x16)
    const int brr = tid >> 4,        bc2 = tid & 15;       // B: rows brr, brr+8, ... (x8)

    float2  ra[16];
    uint32_t rbh[8], rbl[8];

    // prefetch k0 = 0
    #pragma unroll
    for (int it = 0; it < 16; it++) {
        int r = arr + it*8;
        float2 f = *(const float2*)&A1[(m0 + r)*K + ac2*2];
        if (A2) { float2 f2 = *(const float2*)&A2[(m0 + r)*K + ac2*2]; f.x += f2.x; f.y += f2.y; }
        ra[it] = f;
    }
    #pragma unroll
    for (int it = 0; it < 8; it++) {
        int r = brr + it*8;
        rbh[it] = *(const uint32_t*)&Bh[(n0 + r)*K + bc2*2];
        rbl[it] = *(const uint32_t*)&Bl[(n0 + r)*K + bc2*2];
    }

    float acc[4][4][4] = {};

    for (int k0 = 0; k0 < K; k0 += 32) {
        // drain registers to smem (convert A to hi/lo)
        #pragma unroll
        for (int it = 0; it < 16; it++) {
            int r = arr + it*8;
            float ax = ra[it].x, ay = ra[it].y;
            __half hx = __float2half_rn(ax), hy = __float2half_rn(ay);
            Ah[r][ac2*2]   = hx; Ah[r][ac2*2+1] = hy;
            Al[r][ac2*2]   = __float2half_rn(ax - __half2float(hx));
            Al[r][ac2*2+1] = __float2half_rn(ay - __half2float(hy));
        }
        #pragma unroll
        for (int it = 0; it < 8; it++) {
            int r = brr + it*8;
            *(uint32_t*)&Bhs[r][bc2*2] = rbh[it];
            *(uint32_t*)&Bls[r][bc2*2] = rbl[it];
        }
        __syncthreads();

        // prefetch next k-tile while computing this one
        if (k0 + 32 < K) {
            int kn = k0 + 32;
            #pragma unroll
            for (int it = 0; it < 16; it++) {
                int r = arr + it*8;
                float2 f = *(const float2*)&A1[(m0 + r)*K + kn + ac2*2];
                if (A2) { float2 f2 = *(const float2*)&A2[(m0 + r)*K + kn + ac2*2]; f.x += f2.x; f.y += f2.y; }
                ra[it] = f;
            }
            #pragma unroll
            for (int it = 0; it < 8; it++) {
                int r = brr + it*8;
                rbh[it] = *(const uint32_t*)&Bh[(n0 + r)*K + kn + bc2*2];
                rbl[it] = *(const uint32_t*)&Bl[(n0 + r)*K + kn + bc2*2];
            }
        }

        #pragma unroll
        for (int kt = 0; kt < 2; kt++) {
            uint32_t ah[4][4], al[4][4], bh[4][2], bl[4][2];
            #pragma unroll
            for (int mt = 0; mt < 4; mt++) {
                int rb = wm*64 + mt*16 + g;
                int c = kt*16 + 2*tc;
                ah[mt][0] = *(const uint32_t*)&Ah[rb    ][c];
                ah[mt][1] = *(const uint32_t*)&Ah[rb + 8][c];
                ah[mt][2] = *(const uint32_t*)&Ah[rb    ][c + 8];
                ah[mt][3] = *(const uint32_t*)&Ah[rb + 8][c + 8];
                al[mt][0] = *(const uint32_t*)&Al[rb    ][c];
                al[mt][1] = *(const uint32_t*)&Al[rb + 8][c];
                al[mt][2] = *(const uint32_t*)&Al[rb    ][c + 8];
                al[mt][3] = *(const uint32_t*)&Al[rb + 8][c + 8];
            }
            #pragma unroll
            for (int nt = 0; nt < 4; nt++) {
                int nb = wn*32 + nt*8 + g;
                int c = kt*16 + 2*tc;
                bh[nt][0] = *(const uint32_t*)&Bhs[nb][c];
                bh[nt][1] = *(const uint32_t*)&Bhs[nb][c + 8];
                bl[nt][0] = *(const uint32_t*)&Bls[nb][c];
                bl[nt][1] = *(const uint32_t*)&Bls[nb][c + 8];
            }
            #pragma unroll
            for (int mt = 0; mt < 4; mt++)
                #pragma unroll
                for (int nt = 0; nt < 4; nt++) {
                    mma16816(acc[mt][nt], ah[mt], bh[nt]);
                    mma16816(acc[mt][nt], al[mt], bh[nt]);
                    mma16816(acc[mt][nt], ah[mt], bl[nt]);
                }
        }
        __syncthreads();
    }

    #pragma unroll
    for (int mt = 0; mt < 4; mt++) {
        int row = m0 + wm*64 + mt*16 + g;
        #pragma unroll
        for (int nt = 0; nt < 4; nt++) {
            int col = n0 + wn*32 + nt*8 + 2*tc;
            float b0 = bias[col], b1 = bias[col + 1];
            float v0 = acc[mt][nt][0] + b0, v1 = acc[mt][nt][1] + b1;
            float v2 = acc[mt][nt][2] + b0, v3 = acc[mt][nt][3] + b1;
            if (relu) {
                v0 = fmaxf(v0, 0.f); v1 = fmaxf(v1, 0.f);
                v2 = fmaxf(v2, 0.f); v3 = fmaxf(v3, 0.f);
            }
            if (OUTHALF) {
                __half* C = (__half*)Cv;
                *(__half2*)&C[row*Nout + col]       = __floats2half2_rn(v0, v1);
                *(__half2*)&C[(row + 8)*Nout + col] = __floats2half2_rn(v2, v3);
            } else {
                float* C = (float*)Cv;
                *(float2*)&C[row*Nout + col]       = make_float2(v0, v1);
                *(float2*)&C[(row + 8)*Nout + col] = make_float2(v2, v3);
            }
        }
    }
}

__global__ void __launch_bounds__(128) gemm_mma_kernel(
    const float* __restrict__ A1, const float* __restrict__ A2,
    const __half* __restrict__ Bh, const __half* __restrict__ Bl,
    const float* __restrict__ bias, float* __restrict__ C,
    int Nout, int K, int relu)
{
    gemm_mma_body<false>(A1, A2, Bh, Bl, bias, C, Nout, K, relu,
                         blockIdx.y*128, blockIdx.x*64);
}

__global__ void __launch_bounds__(128) qkv_mma_kernel(
    const float* __restrict__ A, const __half* __restrict__ wh,
    const __half* __restrict__ wl,
    const float* __restrict__ bq, const float* __restrict__ bk,
    const float* __restrict__ bv, int l)
{
    const __half *Bh, *Bl; const float* bias; __half* C;
    int woff = l*CC*CC;
    if (blockIdx.z == 0)      { Bh = wh + OFF_WQ + woff; Bl = wl + OFF_WQ + woff; bias = bq; C = g_qh; }
    else if (blockIdx.z == 1) { Bh = wh + OFF_WK + woff; Bl = wl + OFF_WK + woff; bias = bk; C = g_kh; }
    else                      { Bh = wh + OFF_WV + woff; Bl = wl + OFF_WV + woff; bias = bv; C = g_vh; }
    gemm_mma_body<true>(A, nullptr, Bh, Bl, bias, C, CC, CC, 0,
                        blockIdx.y*128, blockIdx.x*64);
}

// ---------------- flash attention (fp16, online softmax, KV register prefetch) ----------------
#define QPAD 36
#define VPAD 132
__global__ void __launch_bounds__(256) flash_mma_kernel(
    const __half* __restrict__ Q, const __half* __restrict__ Kp,
    const __half* __restrict__ V, float* __restrict__ Og)
{
    __shared__ __half Qs[256][QPAD];
    __shared__ __half Ks[128][QPAD];
    __shared__ __half VTs[32][VPAD];

    const int tid = threadIdx.x;
    const int w = tid >> 5, lane = tid & 31;
    const int g = lane >> 2, tc = lane & 3;
    const int hoff = blockIdx.y * DHH;
    const int q0 = blockIdx.x * 256;
    const __half2 qsc2 = __float2half2_rn(QSC);

    // staging coordinates (x8 rows per thread)
    const int kr = tid >> 4, kc2 = tid & 15;   // K rows kr + it*16
    const int vj = tid >> 4, vdp = tid & 15;   // V keys vj + it*16

    #pragma unroll
    for (int it = 0; it < 16; it++) {
        int idx = it*256 + tid;
        int r = idx >> 4, pr = idx & 15;
        __half2 h2 = *(const __half2*)&Q[(q0 + r)*CC + hoff + pr*2];
        *(__half2*)&Qs[r][pr*2] = __hmul2(h2, qsc2);
    }
    __syncthreads();

    uint32_t qa[2][2][4];
    #pragma unroll
    for (int mt = 0; mt < 2; mt++) {
        #pragma unroll
        for (int kt = 0; kt < 2; kt++) {
            int r0 = w*32 + mt*16 + g;
            qa[mt][kt][0] = *(const uint32_t*)&Qs[r0    ][kt*16 + 2*tc    ];
            qa[mt][kt][1] = *(const uint32_t*)&Qs[r0 + 8][kt*16 + 2*tc    ];
            qa[mt][kt][2] = *(const uint32_t*)&Qs[r0    ][kt*16 + 2*tc + 8];
            qa[mt][kt][3] = *(const uint32_t*)&Qs[r0 + 8][kt*16 + 2*tc + 8];
        }
    }

    float oacc[2][4][4] = {};
    float lacc[4] = {};
    float mrow[4] = {-1e30f, -1e30f, -1e30f, -1e30f};

    uint32_t rk[8], rv[8];
    // prefetch block 0
    #pragma unroll
    for (int it = 0; it < 8; it++) {
        rk[it] = *(const uint32_t*)&Kp[(kr + it*16)*CC + hoff + kc2*2];
        rv[it] = *(const uint32_t*)&V [(vj + it*16)*CC + hoff + vdp*2];
    }

    for (int j0 = 0; j0 < NN; j0 += 128) {
        __syncthreads();   // prev block's smem reads complete
        #pragma unroll
        for (int it = 0; it < 8; it++) {
            *(uint32_t*)&Ks[kr + it*16][kc2*2] = rk[it];
            __half2 h2 = *(__half2*)&rv[it];
            VTs[vdp*2    ][vj + it*16] = __low2half(h2);
            VTs[vdp*2 + 1][vj + it*16] = __high2half(h2);
        }
        __syncthreads();

        // prefetch next block during compute
        if (j0 + 128 < NN) {
            int jn = j0 + 128;
            #pragma unroll
            for (int it = 0; it < 8; it++) {
                rk[it] = *(const uint32_t*)&Kp[(jn + kr + it*16)*CC + hoff + kc2*2];
                rv[it] = *(const uint32_t*)&V [(jn + vj + it*16)*CC + hoff + vdp*2];
            }
        }

        #pragma unroll
        for (int ng = 0; ng < 8; ng++) {
            const int kb = ng*16;
            float s[2][2][4] = {};
            #pragma unroll
            for (int kt = 0; kt < 2; kt++) {
                uint32_t b[2][2];
                #pragma unroll
                for (int j = 0; j < 2; j++) {
                    int key = kb + j*8 + g;
                    b[j][0] = *(const uint32_t*)&Ks[key][kt*16 + 2*tc    ];
                    b[j][1] = *(const uint32_t*)&Ks[key][kt*16 + 2*tc + 8];
                }
                #pragma unroll
                for (int mt = 0; mt < 2; mt++)
                    #pragma unroll
                    for (int j = 0; j < 2; j++)
                        mma16816(s[mt][j], qa[mt][kt], b[j]);
            }
            uint32_t pa[2][4];
            #pragma unroll
            for (int mt = 0; mt < 2; mt++) {
                #pragma unroll
                for (int hi = 0; hi < 2; hi++) {
                    float rm = fmaxf(fmaxf(s[mt][0][2*hi], s[mt][0][2*hi+1]),
                                     fmaxf(s[mt][1][2*hi], s[mt][1][2*hi+1]));
                    rm = fmaxf(rm, __shfl_xor_sync(0xffffffffu, rm, 1));
                    rm = fmaxf(rm, __shfl_xor_sync(0xffffffffu, rm, 2));
                    float mold = mrow[mt*2 + hi];
                    float mnew = fmaxf(mold, rm);
                    float p00 = ex2(s[mt][0][2*hi]   - mnew);
                    float p01 = ex2(s[mt][0][2*hi+1] - mnew);
                    float p10 = ex2(s[mt][1][2*hi]   - mnew);
                    float p11 = ex2(s[mt][1][2*hi+1] - mnew);
                    float psum = p00 + p01 + p10 + p11;
                    if (rm > mold) {
                        float cf = ex2(mold - mnew);
                        mrow[mt*2 + hi] = mnew;
                        lacc[mt*2 + hi] = lacc[mt*2 + hi]*cf + psum;
                        #pragma unroll
                        for (int dj = 0; dj < 4; dj++) {
                            oacc[mt][dj][2*hi]   *= cf;
                            oacc[mt][dj][2*hi+1] *= cf;
                        }
                    } else {
                        lacc[mt*2 + hi] += psum;
                    }
                    pa[mt][0*2 + hi] = packh2(p00, p01);
                    pa[mt][1*2 + hi] = packh2(p10, p11);
                }
            }
            #pragma unroll
            for (int dj = 0; dj < 4; dj++) {
                uint32_t vb[2];
                vb[0] = *(const uint32_t*)&VTs[dj*8 + g][kb + 2*tc    ];
                vb[1] = *(const uint32_t*)&VTs[dj*8 + g][kb + 2*tc + 8];
                #pragma unroll
                for (int mt = 0; mt < 2; mt++)
                    mma16816(oacc[mt][dj], pa[mt], vb);
            }
        }
    }

    #pragma unroll
    for (int i = 0; i < 4; i++) {
        lacc[i] += __shfl_xor_sync(0xffffffffu, lacc[i], 1);
        lacc[i] += __shfl_xor_sync(0xffffffffu, lacc[i], 2);
    }
    #pragma unroll
    for (int mt = 0; mt < 2; mt++) {
        int rbase = q0 + w*32 + mt*16;
        float inv0 = 1.f / lacc[mt*2 + 0];
        float inv1 = 1.f / lacc[mt*2 + 1];
        #pragma unroll
        for (int dj = 0; dj < 4; dj++) {
            int col = hoff + dj*8 + 2*tc;
            *(float2*)&Og[(rbase + g    )*CC + col] =
                make_float2(oacc[mt][dj][0]*inv0, oacc[mt][dj][1]*inv0);
            *(float2*)&Og[(rbase + g + 8)*CC + col] =
                make_float2(oacc[mt][dj][2]*inv1, oacc[mt][dj][3]*inv1);
        }
    }
}

// ---------------- small kernels ----------------
__global__ void lin1_kernel(const float* __restrict__ x, const float* __restrict__ w,
                            const float* __restrict__ b) {
    int n = blockIdx.x, c = threadIdx.x;
    g_h[n*CC + c] = x[n]*w[c] + b[c];
}

__global__ void zero_stats_kernel() {
    int i = blockIdx.x*256 + threadIdx.x;
    g_sum[i] = 0.f;
    g_sumsq[i] = 0.f;
    if (blockIdx.x == 0 && threadIdx.x < 9) g_cnt[threadIdx.x] = 0;
}

// ---------------- fused BN: stats + grid-sync + apply ----------------
__global__ void __launch_bounds__(256) bn_fused_kernel(
    const float* __restrict__ in1, const float* __restrict__ in2,
    int slot,
    const float* __restrict__ gamma, const float* __restrict__ beta,
    const float* __restrict__ addend, float* __restrict__ out)
{
    const int c = threadIdx.x;
    const int r0 = blockIdx.x * 32;
    const int statoff = slot * CC;

    float v[32];
    float s = 0.f, ss = 0.f;
    #pragma unroll 4
    for (int i = 0; i < 32; i++) {
        float x = in1[(r0 + i)*CC + c] + in2[(r0 + i)*CC + c];
        v[i] = x;
        s += x; ss += x*x;
    }
    atomicAdd(&g_sum[statoff + c], s);
    atomicAdd(&g_sumsq[statoff + c], ss);
    __threadfence();
    __syncthreads();
    if (threadIdx.x == 0) atomicAdd(&g_cnt[slot], 1);
    if (threadIdx.x == 0) {
        while (atomicAdd(&g_cnt[slot], 0) < (int)gridDim.x) { }
    }
    __syncthreads();

    float mean = g_sum[statoff + c] * (1.f/NN);
    float var  = g_sumsq[statoff + c] * (1.f/NN) - mean*mean;
    float scale = rsqrtf(var + EPSV) * gamma[c];
    float shift = beta[c] - mean * scale;
    #pragma unroll 4
    for (int i = 0; i < 32; i++) {
        float r = v[i] * scale + shift;
        if (addend) r += addend[(r0 + i)*CC + c];
        out[(r0 + i)*CC + c] = r;
    }
}

// ---------------- host ----------------
extern "C" void kernel_launch(void* const* d_in, const int* in_sizes, int n_in,
                              void* d_out, int out_size) {
    const float* x      = (const float*)d_in[0];
    const int*   ei     = (const int*)  d_in[1];
    const float* lin1_w = (const float*)d_in[2];
    const float* lin1_b = (const float*)d_in[3];
    const float* gin_b1 = (const float*)d_in[5];
    const float* gin_b2 = (const float*)d_in[7];
    const float* bq = (const float*)d_in[12];
    const float* bk = (const float*)d_in[13];
    const float* bv = (const float*)d_in[14];
    const float* bo = (const float*)d_in[15];
    const float* bn1_g = (const float*)d_in[16];
    const float* bn1_b = (const float*)d_in[17];
    const float* bn2_g = (const float*)d_in[18];
    const float* bn2_b = (const float*)d_in[19];
    const float* bn3_g = (const float*)d_in[20];
    const float* bn3_b = (const float*)d_in[21];
    const float* mb1 = (const float*)d_in[23];
    const float* mb2 = (const float*)d_in[25];
    int E = in_sizes[1] / 2;

    float *h, *agg, *t1, *t2, *q, *t3, *o, *h1;
    cudaGetSymbolAddress((void**)&h,   g_h);
    cudaGetSymbolAddress((void**)&agg, g_agg);
    cudaGetSymbolAddress((void**)&t1,  g_t1);
    cudaGetSymbolAddress((void**)&t2,  g_t2);
    cudaGetSymbolAddress((void**)&q,   g_q);
    cudaGetSymbolAddress((void**)&t3,  g_t3);
    cudaGetSymbolAddress((void**)&o,   g_o);
    cudaGetSymbolAddress((void**)&h1,  g_h1);
    __half *wh, *wl, *qh, *kh, *vh;
    cudaGetSymbolAddress((void**)&wh, g_wh);
    cudaGetSymbolAddress((void**)&wl, g_wl);
    cudaGetSymbolAddress((void**)&qh, g_qh);
    cudaGetSymbolAddress((void**)&kh, g_kh);
    cudaGetSymbolAddress((void**)&vh, g_vh);

    convw_all_kernel<<<(TOTW + 255)/256, 256>>>(
        (const float*)d_in[4], (const float*)d_in[6],
        (const float*)d_in[8], (const float*)d_in[9],
        (const float*)d_in[10], (const float*)d_in[11],
        (const float*)d_in[22], (const float*)d_in[24]);
    zero_stats_kernel<<<9, 256>>>();
    csr_zero_kernel<<<NN/256, 256>>>();
    csr_hist_kernel<<<(E + 255)/256, 256>>>(ei, E);
    csr_scan_kernel<<<1, 1024>>>();
    csr_fill_kernel<<<(E + 255)/256, 256>>>(ei, E);

    dim3 gN256(CC/64,   NN/128);
    dim3 gN512(2*CC/64, NN/128);
    dim3 gqkv (CC/64,   NN/128, 3);

    lin1_kernel<<<NN, CC>>>(x, lin1_w, lin1_b);

    for (int l = 0; l < LL; l++) {
        int w1 = l*CC*CC, w2 = l*2*CC*CC;
        int sl = l*3;
        // ---- GIN branch ----
        gather_kernel<<<NN/4, 256>>>();
        gemm_mma_kernel<<<gN256, 128>>>(h, agg, wh + OFF_GW1 + w1, wl + OFF_GW1 + w1,
                                        gin_b1 + l*CC, t1, CC, CC, 1);
        gemm_mma_kernel<<<gN256, 128>>>(t1, nullptr, wh + OFF_GW2 + w1, wl + OFF_GW2 + w1,
                                        gin_b2 + l*CC, t2, CC, CC, 0);
        bn_fused_kernel<<<128, 256>>>(t2, h, sl, bn1_g + l*CC, bn1_b + l*CC, nullptr, h1);
        // ---- global attention ----
        qkv_mma_kernel<<<gqkv, 128>>>(h, wh, wl, bq + l*CC, bk + l*CC, bv + l*CC, l);
        flash_mma_kernel<<<dim3(NN/256, HH), 256>>>(qh, kh, vh, o);
        gemm_mma_kernel<<<gN256, 128>>>(o, nullptr, wh + OFF_WO + w1, wl + OFF_WO + w1,
                                        bo + l*CC, t3, CC, CC, 0);
        bn_fused_kernel<<<128, 256>>>(t3, h, sl + 1, bn2_g + l*CC, bn2_b + l*CC, h1, q);
        // ---- feedforward ----
        gemm_mma_kernel<<<gN512, 128>>>(q, nullptr, wh + OFF_MW1 + w2, wl + OFF_MW1 + w2,
                                        mb1 + l*2*CC, t1, 2*CC, CC, 1);
        gemm_mma_kernel<<<gN256, 128>>>(t1, nullptr, wh + OFF_MW2 + w2, wl + OFF_MW2 + w2,
                                        mb2 + l*CC, t2, CC, 2*CC, 0);
        bn_fused_kernel<<<128, 256>>>(t2, q, sl + 2, bn3_g + l*CC, bn3_b + l*CC, nullptr,
                                      (l == LL-1) ? (float*)d_out : h);
    }
    (void)n_in; (void)out_size;
}